// round 10
// baseline (speedup 1.0000x reference)
#include <cuda_runtime.h>
#include <cuda_bf16.h>
#include <cstdint>
#include <math.h>

// ---------------- problem constants ----------------
#define BB    2
#define TT    1024
#define DD    1024
#define HH    16
#define HDIM  64
#define LL    4
#define DFFN  4096
#define NVOC  16384
#define NTOK  (BB*TT)          // 2048
#define NZ    (BB*HH)          // 32
#define EPSS  1e-6f

// ---------------- scratch (device globals; no allocations allowed) --------
__device__ float g_x[NTOK*DD];
__device__ float g_q[NTOK*DD];
__device__ float g_k[NTOK*DD];
__device__ float g_v[NTOK*DD];
__device__ float g_ot[(long)NZ*TT*HDIM];
__device__ float g_sc[(long)NZ*TT*TT];           // 128 MB attention scores
__device__ float g_u[NTOK*DFFN];
__device__ float g_t[NTOK*DFFN];
__device__ float g_cos[NTOK*(HDIM/2)];
__device__ float g_sin[NTOK*(HDIM/2)];

// bf16 hi/lo activation buffers
__device__ __nv_bfloat16 a_h[NTOK*DD],  a_l[NTOK*DD];
__device__ __nv_bfloat16 u_h[NTOK*DFFN], u_l[NTOK*DFFN];
__device__ __nv_bfloat16 qh_h[(long)NZ*TT*HDIM], qh_l[(long)NZ*TT*HDIM];
__device__ __nv_bfloat16 kh_h[(long)NZ*TT*HDIM], kh_l[(long)NZ*TT*HDIM];
__device__ __nv_bfloat16 vt_h[(long)NZ*HDIM*TT], vt_l[(long)NZ*HDIM*TT];
__device__ __nv_bfloat16 p_h[(long)NZ*TT*TT],   p_l[(long)NZ*TT*TT];

// bf16 hi/lo weight buffers (converted each launch)
__device__ __nv_bfloat16 wq_h[LL*DD*DD],  wq_l[LL*DD*DD];
__device__ __nv_bfloat16 wk_h[LL*DD*DD],  wk_l[LL*DD*DD];
__device__ __nv_bfloat16 wv_h[LL*DD*DD],  wv_l[LL*DD*DD];
__device__ __nv_bfloat16 wo_h[LL*DD*DD],  wo_l[LL*DD*DD];
__device__ __nv_bfloat16 w1_h[(long)LL*DFFN*DD], w1_l[(long)LL*DFFN*DD];
__device__ __nv_bfloat16 w3_h[(long)LL*DFFN*DD], w3_l[(long)LL*DFFN*DD];
__device__ __nv_bfloat16 w2_h[(long)LL*DD*DFFN], w2_l[(long)LL*DD*DFFN];
__device__ __nv_bfloat16 emb_h[NVOC*DD], emb_l[NVOC*DD];

// ---------------- small helpers ----------------
__device__ __forceinline__ uint32_t smem_to_u32(const void* p) {
    uint32_t a;
    asm("{ .reg .u64 t; cvta.to.shared.u64 t, %1; cvt.u32.u64 %0, t; }"
        : "=r"(a) : "l"(p));
    return a;
}
__device__ __forceinline__ uint32_t bf16pack(float a, float b) {
    __nv_bfloat162 t = __floats2bfloat162_rn(a, b);
    return *reinterpret_cast<uint32_t*>(&t);
}
// split 4 floats -> hi uint2, lo uint2
__device__ __forceinline__ void split4(float4 v, uint2& hi, uint2& lo) {
    float h0 = __bfloat162float(__float2bfloat16(v.x));
    float h1 = __bfloat162float(__float2bfloat16(v.y));
    float h2 = __bfloat162float(__float2bfloat16(v.z));
    float h3 = __bfloat162float(__float2bfloat16(v.w));
    hi.x = bf16pack(h0, h1);          hi.y = bf16pack(h2, h3);
    lo.x = bf16pack(v.x-h0, v.y-h1);  lo.y = bf16pack(v.z-h2, v.w-h3);
}

// ================= warp MMA + cp.async helpers (sm_80+) ====================
__device__ __forceinline__ void ldsm_x4(uint32_t* r, uint32_t addr) {
    asm volatile("ldmatrix.sync.aligned.m8n8.x4.shared.b16 {%0,%1,%2,%3}, [%4];"
        : "=r"(r[0]), "=r"(r[1]), "=r"(r[2]), "=r"(r[3]) : "r"(addr));
}
__device__ __forceinline__ void ldsm_x2(uint32_t* r, uint32_t addr) {
    asm volatile("ldmatrix.sync.aligned.m8n8.x2.shared.b16 {%0,%1}, [%2];"
        : "=r"(r[0]), "=r"(r[1]) : "r"(addr));
}
__device__ __forceinline__ void mma_bf16(float* d, const uint32_t* a, const uint32_t* b) {
    asm volatile("mma.sync.aligned.m16n8k16.row.col.f32.bf16.bf16.f32 "
        "{%0,%1,%2,%3}, {%4,%5,%6,%7}, {%8,%9}, {%0,%1,%2,%3};"
        : "+f"(d[0]), "+f"(d[1]), "+f"(d[2]), "+f"(d[3])
        : "r"(a[0]), "r"(a[1]), "r"(a[2]), "r"(a[3]), "r"(b[0]), "r"(b[1]));
}
__device__ __forceinline__ void cp_async16(uint32_t dst, const void* src) {
    asm volatile("cp.async.cg.shared.global [%0], [%1], 16;" :: "r"(dst), "l"(src));
}
#define CP_COMMIT() asm volatile("cp.async.commit_group;" ::: "memory")
#define CP_WAIT1()  asm volatile("cp.async.wait_group 1;" ::: "memory")

// ================= elementwise / prep kernels ===============================
__global__ void embed_gather_kernel(const int* __restrict__ tok,
                                    const float* __restrict__ emb,
                                    float* __restrict__ x) {
    int idx = blockIdx.x * blockDim.x + threadIdx.x;     // NTOK*DD/4
    if (idx >= NTOK*DD/4) return;
    int row = idx >> 8, d4 = idx & 255;
    reinterpret_cast<float4*>(x)[idx] =
        reinterpret_cast<const float4*>(emb + (long)tok[row]*DD)[d4];
}

__global__ void rope_table_kernel(const int* __restrict__ pos,
                                  float* __restrict__ cb, float* __restrict__ sb) {
    int idx = blockIdx.x * blockDim.x + threadIdx.x;
    if (idx >= NTOK*(HDIM/2)) return;
    int row = idx >> 5, i = idx & 31;
    double inv = exp(-((double)(2*i) / (double)HDIM) * log(10000.0));
    double ang = (double)pos[row] * inv;
    cb[idx] = (float)cos(ang);
    sb[idx] = (float)sin(ang);
}

__global__ void convert_split_kernel(const float* __restrict__ src,
                                     __nv_bfloat16* __restrict__ dh,
                                     __nv_bfloat16* __restrict__ dl, long n4) {
    long idx = (long)blockIdx.x * blockDim.x + threadIdx.x;
    if (idx >= n4) return;
    float4 v = reinterpret_cast<const float4*>(src)[idx];
    uint2 hi, lo; split4(v, hi, lo);
    reinterpret_cast<uint2*>(dh)[idx] = hi;
    reinterpret_cast<uint2*>(dl)[idx] = lo;
}

__global__ void rmsnorm_bf16_kernel(const float* __restrict__ x,
                                    const float* __restrict__ w,
                                    __nv_bfloat16* __restrict__ oh,
                                    __nv_bfloat16* __restrict__ ol) {
    int row = blockIdx.x;
    int tid = threadIdx.x;
    const float4* xr = reinterpret_cast<const float4*>(x + (long)row*DD);
    float4 v = xr[tid];
    __shared__ float red[256];
    float s = v.x*v.x + v.y*v.y + v.z*v.z + v.w*v.w;
    red[tid] = s; __syncthreads();
    for (int off = 128; off > 0; off >>= 1) {
        if (tid < off) red[tid] += red[tid + off];
        __syncthreads();
    }
    float inv = rsqrtf(red[0] / (float)DD + EPSS);
    float4 wv = reinterpret_cast<const float4*>(w)[tid];
    float4 o = make_float4(v.x*inv*wv.x, v.y*inv*wv.y, v.z*inv*wv.z, v.w*inv*wv.w);
    uint2 hi, lo; split4(o, hi, lo);
    reinterpret_cast<uint2*>(oh + (long)row*DD)[tid] = hi;
    reinterpret_cast<uint2*>(ol + (long)row*DD)[tid] = lo;
}

// rope + reshape to head layout [z][t][64] (hi/lo)
__global__ void rope_convert_qk_kernel(const float* __restrict__ q,
                                       const float* __restrict__ k,
                                       const float* __restrict__ cb,
                                       const float* __restrict__ sb) {
    int idx = blockIdx.x * blockDim.x + threadIdx.x;
    if (idx >= NTOK*HH*32) return;
    int row = idx >> 9, rem = idx & 511, h = rem >> 5, i = rem & 31;
    float c = cb[row*32 + i], s = sb[row*32 + i];
    int b = row >> 10, t = row & 1023;
    long src = (long)row*DD + h*HDIM + 2*i;
    long dst = ((long)(b*HH + h) * TT + t) * HDIM + 2*i;
    float2 qv = *reinterpret_cast<const float2*>(q + src);
    float2 kv = *reinterpret_cast<const float2*>(k + src);
    float q0 = qv.x*c - qv.y*s, q1 = qv.x*s + qv.y*c;
    float k0 = kv.x*c - kv.y*s, k1 = kv.x*s + kv.y*c;
    float q0h = __bfloat162float(__float2bfloat16(q0));
    float q1h = __bfloat162float(__float2bfloat16(q1));
    float k0h = __bfloat162float(__float2bfloat16(k0));
    float k1h = __bfloat162float(__float2bfloat16(k1));
    *reinterpret_cast<uint32_t*>(&qh_h[dst]) = bf16pack(q0h, q1h);
    *reinterpret_cast<uint32_t*>(&qh_l[dst]) = bf16pack(q0-q0h, q1-q1h);
    *reinterpret_cast<uint32_t*>(&kh_h[dst]) = bf16pack(k0h, k1h);
    *reinterpret_cast<uint32_t*>(&kh_l[dst]) = bf16pack(k0-k0h, k1-k1h);
}

// V -> Vt [z][hd][s] hi/lo (transposed for PV B-operand); 2 s-elems per thread
__global__ void vt_convert_kernel(const float* __restrict__ v) {
    long idx2 = (long)blockIdx.x * blockDim.x + threadIdx.x;   // NZ*HDIM*TT/2
    if (idx2 >= (long)NZ*HDIM*TT/2) return;
    long idx = idx2 * 2;
    int z = (int)(idx >> 16);
    int rem = (int)(idx & 65535);
    int hd = rem >> 10, s = rem & 1023;
    int b = z >> 4, h = z & 15;
    float v0 = v[((long)b*TT + s  )*DD + h*HDIM + hd];
    float v1 = v[((long)b*TT + s+1)*DD + h*HDIM + hd];
    float h0 = __bfloat162float(__float2bfloat16(v0));
    float h1 = __bfloat162float(__float2bfloat16(v1));
    *reinterpret_cast<uint32_t*>(&vt_h[idx]) = bf16pack(h0, h1);
    *reinterpret_cast<uint32_t*>(&vt_l[idx]) = bf16pack(v0-h0, v1-h1);
}

// o [z][t][64] -> a_h/a_l [b*T+t][D]; 4 elems per thread
__global__ void o_convert_kernel(const float* __restrict__ ot) {
    int idx = blockIdx.x * blockDim.x + threadIdx.x;     // NTOK*DD/4
    if (idx >= NTOK*DD/4) return;
    int row = idx >> 8, c4 = (idx & 255) * 4;
    int h = c4 >> 6, hd = c4 & 63;
    int b = row >> 10, t = row & 1023;
    float4 v = *reinterpret_cast<const float4*>(
        ot + ((long)(b*HH + h)*TT + t)*HDIM + hd);
    uint2 hi, lo; split4(v, hi, lo);
    reinterpret_cast<uint2*>(a_h)[idx] = hi;
    reinterpret_cast<uint2*>(a_l)[idx] = lo;
}

__global__ void softmax_bf16_kernel(const float* __restrict__ sc) {
    long row = blockIdx.x;
    int tid = threadIdx.x;
    float4 v = reinterpret_cast<const float4*>(sc + row*TT)[tid];
    __shared__ float red[256];
    float m = fmaxf(fmaxf(v.x, v.y), fmaxf(v.z, v.w));
    red[tid] = m; __syncthreads();
    for (int off = 128; off > 0; off >>= 1) {
        if (tid < off) red[tid] = fmaxf(red[tid], red[tid+off]);
        __syncthreads();
    }
    m = red[0]; __syncthreads();
    v.x = expf(v.x - m); v.y = expf(v.y - m);
    v.z = expf(v.z - m); v.w = expf(v.w - m);
    red[tid] = v.x + v.y + v.z + v.w; __syncthreads();
    for (int off = 128; off > 0; off >>= 1) {
        if (tid < off) red[tid] += red[tid+off];
        __syncthreads();
    }
    float inv = 1.f / red[0];
    v.x *= inv; v.y *= inv; v.z *= inv; v.w *= inv;
    uint2 hi, lo; split4(v, hi, lo);
    reinterpret_cast<uint2*>(p_h + row*TT)[tid] = hi;
    reinterpret_cast<uint2*>(p_l + row*TT)[tid] = lo;
}

__global__ void swiglu_bf16_kernel(const float* __restrict__ u,
                                   const float* __restrict__ t) {
    long idx = (long)blockIdx.x * blockDim.x + threadIdx.x;   // NTOK*DFFN/4
    if (idx >= (long)NTOK*DFFN/4) return;
    float4 uv = reinterpret_cast<const float4*>(u)[idx];
    float4 tv = reinterpret_cast<const float4*>(t)[idx];
    float4 g;
    g.x = uv.x / (1.f + expf(-uv.x)) * tv.x;
    g.y = uv.y / (1.f + expf(-uv.y)) * tv.y;
    g.z = uv.z / (1.f + expf(-uv.z)) * tv.z;
    g.w = uv.w / (1.f + expf(-uv.w)) * tv.w;
    uint2 hi, lo; split4(g, hi, lo);
    reinterpret_cast<uint2*>(u_h)[idx] = hi;
    reinterpret_cast<uint2*>(u_l)[idx] = lo;
}

// ================= bf16x3 GEMM via mma.sync + cp.async pipeline =============
// C[M,N](+z) = alpha * A[M,K] * B[N,K]^T (+ Res), 3-term bf16 split.
// BM=128, BK=32 per stage, 2-stage cp.async double buffer. 256 thr = 8 warps.
// SMEM rows padded to 80B (5x16B) -> conflict-free ldmatrix phases.
template<int BN, int WM, int WN>
__global__ void __launch_bounds__(256, 2)
gemm_mma_kernel(const __nv_bfloat16* __restrict__ Ah,
                const __nv_bfloat16* __restrict__ Al, long lda, long strideAz,
                const __nv_bfloat16* __restrict__ Bh,
                const __nv_bfloat16* __restrict__ Bl, long ldb, long strideBz,
                float* __restrict__ C, long ldc, long strideCz,
                const float* __restrict__ Res,
                int K, float alpha)
{
    constexpr int BM = 128;
    constexpr int MF = WM / 16;
    constexpr int NF = WN / 8;
    constexpr int WMS = BM / WM;
    constexpr int ROWB = 80;
    constexpr int ASZ = BM * ROWB;          // per-term A bytes
    constexpr int BSZ = BN * ROWB;
    constexpr int STAGE = 2*ASZ + 2*BSZ;

    extern __shared__ char smem[];
    const uint32_t s0 = smem_to_u32(smem);

    int tid = threadIdx.x, wid = tid >> 5, lane = tid & 31;
    int wm = wid % WMS, wn = wid / WMS;
    int z = blockIdx.z;
    Ah += (long)z * strideAz;  Al += (long)z * strideAz;
    Bh += (long)z * strideBz;  Bl += (long)z * strideBz;
    C  += (long)z * strideCz;
    const float* R = Res ? Res + (long)z * strideCz : nullptr;

    const int m0 = blockIdx.y * BM;
    const int n0 = blockIdx.x * BN;

    // prefetch lambda: stage buffer `st`, k offset k0
    auto prefetch = [&](int st, int k0) {
        uint32_t sb = s0 + st * STAGE;
        #pragma unroll
        for (int i = tid; i < BM*8; i += 256) {          // A: 2 terms x 128 x 4
            int term = i >> 9, rem = i & 511;
            int r = rem >> 2, c = rem & 3;
            const __nv_bfloat16* src = (term ? Al : Ah) + (long)(m0 + r)*lda + k0 + c*8;
            cp_async16(sb + term*ASZ + r*ROWB + c*16, src);
        }
        #pragma unroll
        for (int i = tid; i < BN*8; i += 256) {          // B: 2 terms x BN x 4
            int term = i >= BN*4;
            int rem = term ? i - BN*4 : i;
            int r = rem >> 2, c = rem & 3;
            const __nv_bfloat16* src = (term ? Bl : Bh) + (long)(n0 + r)*ldb + k0 + c*8;
            cp_async16(sb + 2*ASZ + term*BSZ + r*ROWB + c*16, src);
        }
    };

    float d[MF][NF][4] = {};
    const int lm16 = lane & 15, lq = lane >> 4;
    const int lb8  = lane & 7,  lh = (lane >> 3) & 1;

    const int nsteps = K >> 5;
    prefetch(0, 0);
    CP_COMMIT();

    for (int s = 0; s < nsteps; s++) {
        if (s + 1 < nsteps) prefetch((s + 1) & 1, (s + 1) << 5);
        CP_COMMIT();
        CP_WAIT1();
        __syncthreads();

        uint32_t sb  = s0 + (s & 1) * STAGE;
        uint32_t sAh = sb, sAl = sb + ASZ;
        uint32_t sBh = sb + 2*ASZ, sBl = sb + 2*ASZ + BSZ;

        #pragma unroll
        for (int kk = 0; kk < 32; kk += 16) {
            uint32_t ah[MF][4], al[MF][4];
            #pragma unroll
            for (int fm = 0; fm < MF; fm++) {
                uint32_t off = (uint32_t)((wm*WM + fm*16 + lm16)*ROWB + (kk + lq*8)*2);
                ldsm_x4(ah[fm], sAh + off);
                ldsm_x4(al[fm], sAl + off);
            }
            #pragma unroll
            for (int fn = 0; fn < NF; fn++) {
                uint32_t bh[2], bl[2];
                uint32_t off = (uint32_t)((wn*WN + fn*8 + lb8)*ROWB + (kk + lh*8)*2);
                ldsm_x2(bh, sBh + off);
                ldsm_x2(bl, sBl + off);
                #pragma unroll
                for (int fm = 0; fm < MF; fm++) {
                    mma_bf16(d[fm][fn], ah[fm], bh);
                    mma_bf16(d[fm][fn], ah[fm], bl);
                    mma_bf16(d[fm][fn], al[fm], bh);
                }
            }
        }
        __syncthreads();
    }

    // ---- epilogue: alpha scale + optional residual ----
    #pragma unroll
    for (int fm = 0; fm < MF; fm++) {
        #pragma unroll
        for (int fn = 0; fn < NF; fn++) {
            long row = m0 + wm*WM + fm*16 + (lane >> 2);
            long col = n0 + wn*WN + fn*8 + (lane & 3)*2;
            float2 v0 = make_float2(d[fm][fn][0]*alpha, d[fm][fn][1]*alpha);
            float2 v1 = make_float2(d[fm][fn][2]*alpha, d[fm][fn][3]*alpha);
            if (R) {
                float2 r0 = *reinterpret_cast<const float2*>(R + row*ldc + col);
                float2 r1 = *reinterpret_cast<const float2*>(R + (row+8)*ldc + col);
                v0.x += r0.x; v0.y += r0.y; v1.x += r1.x; v1.y += r1.y;
            }
            *reinterpret_cast<float2*>(C + row*ldc + col)     = v0;
            *reinterpret_cast<float2*>(C + (row+8)*ldc + col) = v1;
        }
    }
}

// ================= host orchestration =======================================
extern "C" void kernel_launch(void* const* d_in, const int* in_sizes, int n_in,
                              void* d_out, int out_size) {
    const int*   tok     = (const int*)  d_in[0];
    const int*   pos     = (const int*)  d_in[1];
    const float* emb     = (const float*)d_in[2];
    const float* attn_nw = (const float*)d_in[3];
    const float* wq      = (const float*)d_in[4];
    const float* wk      = (const float*)d_in[5];
    const float* wv      = (const float*)d_in[6];
    const float* wo      = (const float*)d_in[7];
    const float* ff_nw   = (const float*)d_in[8];
    const float* w1      = (const float*)d_in[9];
    const float* w2      = (const float*)d_in[10];
    const float* w3      = (const float*)d_in[11];
    const float* norm_w  = (const float*)d_in[12];
    float* out = (float*)d_out;

    float *x, *q, *k, *v, *ot, *sc, *u, *t, *cb, *sb;
    cudaGetSymbolAddress((void**)&x,  g_x);
    cudaGetSymbolAddress((void**)&q,  g_q);
    cudaGetSymbolAddress((void**)&k,  g_k);
    cudaGetSymbolAddress((void**)&v,  g_v);
    cudaGetSymbolAddress((void**)&ot, g_ot);
    cudaGetSymbolAddress((void**)&sc, g_sc);
    cudaGetSymbolAddress((void**)&u,  g_u);
    cudaGetSymbolAddress((void**)&t,  g_t);
    cudaGetSymbolAddress((void**)&cb, g_cos);
    cudaGetSymbolAddress((void**)&sb, g_sin);

    __nv_bfloat16 *ah, *al, *uh, *ul, *qhh, *qhl, *khh, *khl, *vth, *vtl, *ph, *pl;
    cudaGetSymbolAddress((void**)&ah,  a_h);  cudaGetSymbolAddress((void**)&al,  a_l);
    cudaGetSymbolAddress((void**)&uh,  u_h);  cudaGetSymbolAddress((void**)&ul,  u_l);
    cudaGetSymbolAddress((void**)&qhh, qh_h); cudaGetSymbolAddress((void**)&qhl, qh_l);
    cudaGetSymbolAddress((void**)&khh, kh_h); cudaGetSymbolAddress((void**)&khl, kh_l);
    cudaGetSymbolAddress((void**)&vth, vt_h); cudaGetSymbolAddress((void**)&vtl, vt_l);
    cudaGetSymbolAddress((void**)&ph,  p_h);  cudaGetSymbolAddress((void**)&pl,  p_l);

    __nv_bfloat16 *wqh,*wql,*wkh,*wkl,*wvh,*wvl,*woh,*wol,*w1h,*w1l,*w3h,*w3l,*w2h,*w2l,*eh,*el;
    cudaGetSymbolAddress((void**)&wqh, wq_h); cudaGetSymbolAddress((void**)&wql, wq_l);
    cudaGetSymbolAddress((void**)&wkh, wk_h); cudaGetSymbolAddress((void**)&wkl, wk_l);
    cudaGetSymbolAddress((void**)&wvh, wv_h); cudaGetSymbolAddress((void**)&wvl, wv_l);
    cudaGetSymbolAddress((void**)&woh, wo_h); cudaGetSymbolAddress((void**)&wol, wo_l);
    cudaGetSymbolAddress((void**)&w1h, w1_h); cudaGetSymbolAddress((void**)&w1l, w1_l);
    cudaGetSymbolAddress((void**)&w3h, w3_h); cudaGetSymbolAddress((void**)&w3l, w3_l);
    cudaGetSymbolAddress((void**)&w2h, w2_h); cudaGetSymbolAddress((void**)&w2l, w2_l);
    cudaGetSymbolAddress((void**)&eh,  emb_h); cudaGetSymbolAddress((void**)&el,  emb_l);

    const int TPB = 256;
    // dynamic smem sizes: 2 stages of (2*A + 2*B)
    constexpr int SMEM128 = 2 * (2*128*80 + 2*128*80);   // 81920
    constexpr int SMEM64  = 2 * (2*128*80 + 2*64*80);    // 61440
    cudaFuncSetAttribute((const void*)gemm_mma_kernel<128,64,32>,
                         cudaFuncAttributeMaxDynamicSharedMemorySize, SMEM128);
    cudaFuncSetAttribute((const void*)gemm_mma_kernel<64,32,32>,
                         cudaFuncAttributeMaxDynamicSharedMemorySize, SMEM64);

    // ---- weight + embed conversion to bf16 hi/lo (vectorized) ----
    auto conv = [&](const float* s, __nv_bfloat16* dh, __nv_bfloat16* dl, long n) {
        long n4 = n >> 2;
        convert_split_kernel<<<(int)((n4 + TPB-1)/TPB), TPB>>>(s, dh, dl, n4);
    };
    conv(wq, wqh, wql, (long)LL*DD*DD);
    conv(wk, wkh, wkl, (long)LL*DD*DD);
    conv(wv, wvh, wvl, (long)LL*DD*DD);
    conv(wo, woh, wol, (long)LL*DD*DD);
    conv(w1, w1h, w1l, (long)LL*DFFN*DD);
    conv(w3, w3h, w3l, (long)LL*DFFN*DD);
    conv(w2, w2h, w2l, (long)LL*DD*DFFN);
    conv(emb, eh, el,  (long)NVOC*DD);

    embed_gather_kernel<<<(NTOK*DD/4 + TPB-1)/TPB, TPB>>>(tok, emb, x);
    rope_table_kernel<<<(NTOK*32 + TPB-1)/TPB, TPB>>>(pos, cb, sb);

    dim3 gProj(DD/128,   NTOK/128);        // (8,16)
    dim3 gFF  (DFFN/128, NTOK/128);        // (32,16)
    dim3 gHead(NVOC/128, NTOK/128);        // (128,16)
    dim3 gQK  (TT/128, TT/128, NZ);        // (8,8,32)
    dim3 gPV  (1,      TT/128, NZ);        // (1,8,32)

    for (int l = 0; l < LL; l++) {
        long woff  = (long)l*DD*DD;
        long wfoff = (long)l*DFFN*DD;

        // ---- attention ----
        rmsnorm_bf16_kernel<<<NTOK, TPB>>>(x, attn_nw + (long)l*DD, ah, al);
        gemm_mma_kernel<128,64,32><<<gProj, TPB, SMEM128>>>(
            ah, al, DD, 0, wqh+woff, wql+woff, DD, 0, q, DD, 0, nullptr, DD, 1.f);
        gemm_mma_kernel<128,64,32><<<gProj, TPB, SMEM128>>>(
            ah, al, DD, 0, wkh+woff, wkl+woff, DD, 0, k, DD, 0, nullptr, DD, 1.f);
        gemm_mma_kernel<128,64,32><<<gProj, TPB, SMEM128>>>(
            ah, al, DD, 0, wvh+woff, wvl+woff, DD, 0, v, DD, 0, nullptr, DD, 1.f);
        rope_convert_qk_kernel<<<(NTOK*HH*32 + TPB-1)/TPB, TPB>>>(q, k, cb, sb);
        vt_convert_kernel<<<(int)(((long)NZ*HDIM*TT/2 + TPB-1)/TPB), TPB>>>(v);
        gemm_mma_kernel<128,64,32><<<gQK, TPB, SMEM128>>>(
            qhh, qhl, HDIM, (long)TT*HDIM,
            khh, khl, HDIM, (long)TT*HDIM,
            sc, TT, (long)TT*TT, nullptr, HDIM, 0.125f);
        softmax_bf16_kernel<<<NZ*TT, TPB>>>(sc);
        gemm_mma_kernel<64,32,32><<<gPV, TPB, SMEM64>>>(
            ph, pl, TT, (long)TT*TT,
            vth, vtl, TT, (long)HDIM*TT,
            ot, HDIM, (long)TT*HDIM, nullptr, TT, 1.f);
        o_convert_kernel<<<(NTOK*DD/4 + TPB-1)/TPB, TPB>>>(ot);
        gemm_mma_kernel<128,64,32><<<gProj, TPB, SMEM128>>>(
            ah, al, DD, 0, woh+woff, wol+woff, DD, 0, x, DD, 0, x, DD, 1.f);

        // ---- SwiGLU FFN ----
        rmsnorm_bf16_kernel<<<NTOK, TPB>>>(x, ff_nw + (long)l*DD, ah, al);
        gemm_mma_kernel<128,64,32><<<gFF, TPB, SMEM128>>>(
            ah, al, DD, 0, w1h+wfoff, w1l+wfoff, DD, 0, u, DFFN, 0, nullptr, DD, 1.f);
        gemm_mma_kernel<128,64,32><<<gFF, TPB, SMEM128>>>(
            ah, al, DD, 0, w3h+wfoff, w3l+wfoff, DD, 0, t, DFFN, 0, nullptr, DD, 1.f);
        swiglu_bf16_kernel<<<(int)(((long)NTOK*DFFN/4 + TPB-1)/TPB), TPB>>>(u, t);
        gemm_mma_kernel<128,64,32><<<gProj, TPB, SMEM128>>>(
            uh, ul, DFFN, 0, w2h+wfoff, w2l+wfoff, DFFN, 0, x, DD, 0, x, DFFN, 1.f);
    }

    // ---- final norm + tied LM head ----
    rmsnorm_bf16_kernel<<<NTOK, TPB>>>(x, norm_w, ah, al);
    gemm_mma_kernel<128,64,32><<<gHead, TPB, SMEM128>>>(
        ah, al, DD, 0, eh, el, DD, 0, out, NVOC, 0, nullptr, DD, 1.f);
}

// round 11
// speedup vs baseline: 1.0024x; 1.0024x over previous
#include <cuda_runtime.h>
#include <cuda_bf16.h>
#include <cstdint>
#include <math.h>

// ---------------- problem constants ----------------
#define BB    2
#define TT    1024
#define DD    1024
#define HH    16
#define HDIM  64
#define LL    4
#define DFFN  4096
#define NVOC  16384
#define NTOK  (BB*TT)          // 2048
#define NZ    (BB*HH)          // 32
#define EPSS  1e-6f

// ---------------- scratch (device globals; no allocations allowed) --------
__device__ float g_x[NTOK*DD];
__device__ float g_q[NTOK*DD];
__device__ float g_k[NTOK*DD];
__device__ float g_v[NTOK*DD];
__device__ float g_ot[(long)NZ*TT*HDIM];
__device__ float g_sc[(long)NZ*TT*TT];           // 128 MB attention scores
__device__ float g_u[NTOK*DFFN];
__device__ float g_t[NTOK*DFFN];
__device__ float g_cos[NTOK*(HDIM/2)];
__device__ float g_sin[NTOK*(HDIM/2)];

// bf16 hi/lo activation buffers
__device__ __nv_bfloat16 a_h[NTOK*DD],  a_l[NTOK*DD];
__device__ __nv_bfloat16 u_h[NTOK*DFFN], u_l[NTOK*DFFN];
__device__ __nv_bfloat16 qh_h[(long)NZ*TT*HDIM], qh_l[(long)NZ*TT*HDIM];
__device__ __nv_bfloat16 kh_h[(long)NZ*TT*HDIM], kh_l[(long)NZ*TT*HDIM];
__device__ __nv_bfloat16 vt_h[(long)NZ*HDIM*TT], vt_l[(long)NZ*HDIM*TT];
__device__ __nv_bfloat16 p_h[(long)NZ*TT*TT],   p_l[(long)NZ*TT*TT];

// bf16 hi/lo weight buffers (converted each launch)
__device__ __nv_bfloat16 wq_h[LL*DD*DD],  wq_l[LL*DD*DD];
__device__ __nv_bfloat16 wk_h[LL*DD*DD],  wk_l[LL*DD*DD];
__device__ __nv_bfloat16 wv_h[LL*DD*DD],  wv_l[LL*DD*DD];
__device__ __nv_bfloat16 wo_h[LL*DD*DD],  wo_l[LL*DD*DD];
__device__ __nv_bfloat16 w1_h[(long)LL*DFFN*DD], w1_l[(long)LL*DFFN*DD];
__device__ __nv_bfloat16 w3_h[(long)LL*DFFN*DD], w3_l[(long)LL*DFFN*DD];
__device__ __nv_bfloat16 w2_h[(long)LL*DD*DFFN], w2_l[(long)LL*DD*DFFN];
__device__ __nv_bfloat16 emb_h[NVOC*DD], emb_l[NVOC*DD];

// ---------------- small helpers ----------------
__device__ __forceinline__ uint32_t smem_to_u32(const void* p) {
    uint32_t a;
    asm("{ .reg .u64 t; cvta.to.shared.u64 t, %1; cvt.u32.u64 %0, t; }"
        : "=r"(a) : "l"(p));
    return a;
}
__device__ __forceinline__ uint32_t bf16pack(float a, float b) {
    __nv_bfloat162 t = __floats2bfloat162_rn(a, b);
    return *reinterpret_cast<uint32_t*>(&t);
}
// split 4 floats -> hi uint2, lo uint2
__device__ __forceinline__ void split4(float4 v, uint2& hi, uint2& lo) {
    float h0 = __bfloat162float(__float2bfloat16(v.x));
    float h1 = __bfloat162float(__float2bfloat16(v.y));
    float h2 = __bfloat162float(__float2bfloat16(v.z));
    float h3 = __bfloat162float(__float2bfloat16(v.w));
    hi.x = bf16pack(h0, h1);          hi.y = bf16pack(h2, h3);
    lo.x = bf16pack(v.x-h0, v.y-h1);  lo.y = bf16pack(v.z-h2, v.w-h3);
}

// ================= warp MMA + cp.async helpers (sm_80+) ====================
__device__ __forceinline__ void ldsm_x4(uint32_t* r, uint32_t addr) {
    asm volatile("ldmatrix.sync.aligned.m8n8.x4.shared.b16 {%0,%1,%2,%3}, [%4];"
        : "=r"(r[0]), "=r"(r[1]), "=r"(r[2]), "=r"(r[3]) : "r"(addr));
}
__device__ __forceinline__ void ldsm_x2(uint32_t* r, uint32_t addr) {
    asm volatile("ldmatrix.sync.aligned.m8n8.x2.shared.b16 {%0,%1}, [%2];"
        : "=r"(r[0]), "=r"(r[1]) : "r"(addr));
}
__device__ __forceinline__ void mma_bf16(float* d, const uint32_t* a, const uint32_t* b) {
    asm volatile("mma.sync.aligned.m16n8k16.row.col.f32.bf16.bf16.f32 "
        "{%0,%1,%2,%3}, {%4,%5,%6,%7}, {%8,%9}, {%0,%1,%2,%3};"
        : "+f"(d[0]), "+f"(d[1]), "+f"(d[2]), "+f"(d[3])
        : "r"(a[0]), "r"(a[1]), "r"(a[2]), "r"(a[3]), "r"(b[0]), "r"(b[1]));
}
__device__ __forceinline__ void cp_async16(uint32_t dst, const void* src) {
    asm volatile("cp.async.cg.shared.global [%0], [%1], 16;" :: "r"(dst), "l"(src));
}
#define CP_COMMIT() asm volatile("cp.async.commit_group;" ::: "memory")
#define CP_WAIT1()  asm volatile("cp.async.wait_group 1;" ::: "memory")

// ================= elementwise / prep kernels ===============================
__global__ void embed_gather_kernel(const int* __restrict__ tok,
                                    const float* __restrict__ emb,
                                    float* __restrict__ x) {
    int idx = blockIdx.x * blockDim.x + threadIdx.x;     // NTOK*DD/4
    if (idx >= NTOK*DD/4) return;
    int row = idx >> 8, d4 = idx & 255;
    reinterpret_cast<float4*>(x)[idx] =
        reinterpret_cast<const float4*>(emb + (long)tok[row]*DD)[d4];
}

__global__ void rope_table_kernel(const int* __restrict__ pos,
                                  float* __restrict__ cb, float* __restrict__ sb) {
    int idx = blockIdx.x * blockDim.x + threadIdx.x;
    if (idx >= NTOK*(HDIM/2)) return;
    int row = idx >> 5, i = idx & 31;
    double inv = exp(-((double)(2*i) / (double)HDIM) * log(10000.0));
    double ang = (double)pos[row] * inv;
    cb[idx] = (float)cos(ang);
    sb[idx] = (float)sin(ang);
}

__global__ void convert_split_kernel(const float* __restrict__ src,
                                     __nv_bfloat16* __restrict__ dh,
                                     __nv_bfloat16* __restrict__ dl, long n4) {
    long idx = (long)blockIdx.x * blockDim.x + threadIdx.x;
    if (idx >= n4) return;
    float4 v = reinterpret_cast<const float4*>(src)[idx];
    uint2 hi, lo; split4(v, hi, lo);
    reinterpret_cast<uint2*>(dh)[idx] = hi;
    reinterpret_cast<uint2*>(dl)[idx] = lo;
}

__global__ void rmsnorm_bf16_kernel(const float* __restrict__ x,
                                    const float* __restrict__ w,
                                    __nv_bfloat16* __restrict__ oh,
                                    __nv_bfloat16* __restrict__ ol) {
    int row = blockIdx.x;
    int tid = threadIdx.x;
    const float4* xr = reinterpret_cast<const float4*>(x + (long)row*DD);
    float4 v = xr[tid];
    __shared__ float red[256];
    float s = v.x*v.x + v.y*v.y + v.z*v.z + v.w*v.w;
    red[tid] = s; __syncthreads();
    for (int off = 128; off > 0; off >>= 1) {
        if (tid < off) red[tid] += red[tid + off];
        __syncthreads();
    }
    float inv = rsqrtf(red[0] / (float)DD + EPSS);
    float4 wv = reinterpret_cast<const float4*>(w)[tid];
    float4 o = make_float4(v.x*inv*wv.x, v.y*inv*wv.y, v.z*inv*wv.z, v.w*inv*wv.w);
    uint2 hi, lo; split4(o, hi, lo);
    reinterpret_cast<uint2*>(oh + (long)row*DD)[tid] = hi;
    reinterpret_cast<uint2*>(ol + (long)row*DD)[tid] = lo;
}

// rope + reshape to head layout [z][t][64] (hi/lo)
__global__ void rope_convert_qk_kernel(const float* __restrict__ q,
                                       const float* __restrict__ k,
                                       const float* __restrict__ cb,
                                       const float* __restrict__ sb) {
    int idx = blockIdx.x * blockDim.x + threadIdx.x;
    if (idx >= NTOK*HH*32) return;
    int row = idx >> 9, rem = idx & 511, h = rem >> 5, i = rem & 31;
    float c = cb[row*32 + i], s = sb[row*32 + i];
    int b = row >> 10, t = row & 1023;
    long src = (long)row*DD + h*HDIM + 2*i;
    long dst = ((long)(b*HH + h) * TT + t) * HDIM + 2*i;
    float2 qv = *reinterpret_cast<const float2*>(q + src);
    float2 kv = *reinterpret_cast<const float2*>(k + src);
    float q0 = qv.x*c - qv.y*s, q1 = qv.x*s + qv.y*c;
    float k0 = kv.x*c - kv.y*s, k1 = kv.x*s + kv.y*c;
    float q0h = __bfloat162float(__float2bfloat16(q0));
    float q1h = __bfloat162float(__float2bfloat16(q1));
    float k0h = __bfloat162float(__float2bfloat16(k0));
    float k1h = __bfloat162float(__float2bfloat16(k1));
    *reinterpret_cast<uint32_t*>(&qh_h[dst]) = bf16pack(q0h, q1h);
    *reinterpret_cast<uint32_t*>(&qh_l[dst]) = bf16pack(q0-q0h, q1-q1h);
    *reinterpret_cast<uint32_t*>(&kh_h[dst]) = bf16pack(k0h, k1h);
    *reinterpret_cast<uint32_t*>(&kh_l[dst]) = bf16pack(k0-k0h, k1-k1h);
}

// V -> Vt [z][hd][s] hi/lo (transposed for PV B-operand); 2 s-elems per thread
__global__ void vt_convert_kernel(const float* __restrict__ v) {
    long idx2 = (long)blockIdx.x * blockDim.x + threadIdx.x;   // NZ*HDIM*TT/2
    if (idx2 >= (long)NZ*HDIM*TT/2) return;
    long idx = idx2 * 2;
    int z = (int)(idx >> 16);
    int rem = (int)(idx & 65535);
    int hd = rem >> 10, s = rem & 1023;
    int b = z >> 4, h = z & 15;
    float v0 = v[((long)b*TT + s  )*DD + h*HDIM + hd];
    float v1 = v[((long)b*TT + s+1)*DD + h*HDIM + hd];
    float h0 = __bfloat162float(__float2bfloat16(v0));
    float h1 = __bfloat162float(__float2bfloat16(v1));
    *reinterpret_cast<uint32_t*>(&vt_h[idx]) = bf16pack(h0, h1);
    *reinterpret_cast<uint32_t*>(&vt_l[idx]) = bf16pack(v0-h0, v1-h1);
}

// o [z][t][64] -> a_h/a_l [b*T+t][D]; 4 elems per thread
__global__ void o_convert_kernel(const float* __restrict__ ot) {
    int idx = blockIdx.x * blockDim.x + threadIdx.x;     // NTOK*DD/4
    if (idx >= NTOK*DD/4) return;
    int row = idx >> 8, c4 = (idx & 255) * 4;
    int h = c4 >> 6, hd = c4 & 63;
    int b = row >> 10, t = row & 1023;
    float4 v = *reinterpret_cast<const float4*>(
        ot + ((long)(b*HH + h)*TT + t)*HDIM + hd);
    uint2 hi, lo; split4(v, hi, lo);
    reinterpret_cast<uint2*>(a_h)[idx] = hi;
    reinterpret_cast<uint2*>(a_l)[idx] = lo;
}

__global__ void softmax_bf16_kernel(const float* __restrict__ sc) {
    long row = blockIdx.x;
    int tid = threadIdx.x;
    float4 v = reinterpret_cast<const float4*>(sc + row*TT)[tid];
    __shared__ float red[256];
    float m = fmaxf(fmaxf(v.x, v.y), fmaxf(v.z, v.w));
    red[tid] = m; __syncthreads();
    for (int off = 128; off > 0; off >>= 1) {
        if (tid < off) red[tid] = fmaxf(red[tid], red[tid+off]);
        __syncthreads();
    }
    m = red[0]; __syncthreads();
    v.x = expf(v.x - m); v.y = expf(v.y - m);
    v.z = expf(v.z - m); v.w = expf(v.w - m);
    red[tid] = v.x + v.y + v.z + v.w; __syncthreads();
    for (int off = 128; off > 0; off >>= 1) {
        if (tid < off) red[tid] += red[tid+off];
        __syncthreads();
    }
    float inv = 1.f / red[0];
    v.x *= inv; v.y *= inv; v.z *= inv; v.w *= inv;
    uint2 hi, lo; split4(v, hi, lo);
    reinterpret_cast<uint2*>(p_h + row*TT)[tid] = hi;
    reinterpret_cast<uint2*>(p_l + row*TT)[tid] = lo;
}

__global__ void swiglu_bf16_kernel(const float* __restrict__ u,
                                   const float* __restrict__ t) {
    long idx = (long)blockIdx.x * blockDim.x + threadIdx.x;   // NTOK*DFFN/4
    if (idx >= (long)NTOK*DFFN/4) return;
    float4 uv = reinterpret_cast<const float4*>(u)[idx];
    float4 tv = reinterpret_cast<const float4*>(t)[idx];
    float4 g;
    g.x = uv.x / (1.f + expf(-uv.x)) * tv.x;
    g.y = uv.y / (1.f + expf(-uv.y)) * tv.y;
    g.z = uv.z / (1.f + expf(-uv.z)) * tv.z;
    g.w = uv.w / (1.f + expf(-uv.w)) * tv.w;
    uint2 hi, lo; split4(g, hi, lo);
    reinterpret_cast<uint2*>(u_h)[idx] = hi;
    reinterpret_cast<uint2*>(u_l)[idx] = lo;
}

// ================= bf16x3 GEMM via mma.sync + cp.async pipeline =============
// C[M,N](+z) = alpha * A[M,K] * B[N,K]^T (+ Res), 3-term bf16 split.
// BM=128, BK=32 per stage, 2-stage cp.async double buffer. 256 thr = 8 warps.
// SMEM rows padded to 80B (5x16B) -> conflict-free ldmatrix phases.
template<int BN, int WM, int WN>
__global__ void __launch_bounds__(256, 2)
gemm_mma_kernel(const __nv_bfloat16* __restrict__ Ah,
                const __nv_bfloat16* __restrict__ Al, long lda, long strideAz,
                const __nv_bfloat16* __restrict__ Bh,
                const __nv_bfloat16* __restrict__ Bl, long ldb, long strideBz,
                float* __restrict__ C, long ldc, long strideCz,
                const float* __restrict__ Res,
                int K, float alpha)
{
    constexpr int BM = 128;
    constexpr int MF = WM / 16;
    constexpr int NF = WN / 8;
    constexpr int WMS = BM / WM;
    constexpr int ROWB = 80;
    constexpr int ASZ = BM * ROWB;          // per-term A bytes
    constexpr int BSZ = BN * ROWB;
    constexpr int STAGE = 2*ASZ + 2*BSZ;

    extern __shared__ char smem[];
    const uint32_t s0 = smem_to_u32(smem);

    int tid = threadIdx.x, wid = tid >> 5, lane = tid & 31;
    int wm = wid % WMS, wn = wid / WMS;
    int z = blockIdx.z;
    Ah += (long)z * strideAz;  Al += (long)z * strideAz;
    Bh += (long)z * strideBz;  Bl += (long)z * strideBz;
    C  += (long)z * strideCz;
    const float* R = Res ? Res + (long)z * strideCz : nullptr;

    const int m0 = blockIdx.y * BM;
    const int n0 = blockIdx.x * BN;

    // prefetch lambda: stage buffer `st`, k offset k0
    auto prefetch = [&](int st, int k0) {
        uint32_t sb = s0 + st * STAGE;
        #pragma unroll
        for (int i = tid; i < BM*8; i += 256) {          // A: 2 terms x 128 x 4
            int term = i >> 9, rem = i & 511;
            int r = rem >> 2, c = rem & 3;
            const __nv_bfloat16* src = (term ? Al : Ah) + (long)(m0 + r)*lda + k0 + c*8;
            cp_async16(sb + term*ASZ + r*ROWB + c*16, src);
        }
        #pragma unroll
        for (int i = tid; i < BN*8; i += 256) {          // B: 2 terms x BN x 4
            int term = i >= BN*4;
            int rem = term ? i - BN*4 : i;
            int r = rem >> 2, c = rem & 3;
            const __nv_bfloat16* src = (term ? Bl : Bh) + (long)(n0 + r)*ldb + k0 + c*8;
            cp_async16(sb + 2*ASZ + term*BSZ + r*ROWB + c*16, src);
        }
    };

    float d[MF][NF][4] = {};
    const int lm16 = lane & 15, lq = lane >> 4;
    const int lb8  = lane & 7,  lh = (lane >> 3) & 1;

    const int nsteps = K >> 5;
    prefetch(0, 0);
    CP_COMMIT();

    for (int s = 0; s < nsteps; s++) {
        if (s + 1 < nsteps) prefetch((s + 1) & 1, (s + 1) << 5);
        CP_COMMIT();
        CP_WAIT1();
        __syncthreads();

        uint32_t sb  = s0 + (s & 1) * STAGE;
        uint32_t sAh = sb, sAl = sb + ASZ;
        uint32_t sBh = sb + 2*ASZ, sBl = sb + 2*ASZ + BSZ;

        #pragma unroll
        for (int kk = 0; kk < 32; kk += 16) {
            uint32_t ah[MF][4], al[MF][4];
            #pragma unroll
            for (int fm = 0; fm < MF; fm++) {
                uint32_t off = (uint32_t)((wm*WM + fm*16 + lm16)*ROWB + (kk + lq*8)*2);
                ldsm_x4(ah[fm], sAh + off);
                ldsm_x4(al[fm], sAl + off);
            }
            #pragma unroll
            for (int fn = 0; fn < NF; fn++) {
                uint32_t bh[2], bl[2];
                uint32_t off = (uint32_t)((wn*WN + fn*8 + lb8)*ROWB + (kk + lh*8)*2);
                ldsm_x2(bh, sBh + off);
                ldsm_x2(bl, sBl + off);
                #pragma unroll
                for (int fm = 0; fm < MF; fm++) {
                    mma_bf16(d[fm][fn], ah[fm], bh);
                    mma_bf16(d[fm][fn], ah[fm], bl);
                    mma_bf16(d[fm][fn], al[fm], bh);
                }
            }
        }
        __syncthreads();
    }

    // ---- epilogue: alpha scale + optional residual ----
    #pragma unroll
    for (int fm = 0; fm < MF; fm++) {
        #pragma unroll
        for (int fn = 0; fn < NF; fn++) {
            long row = m0 + wm*WM + fm*16 + (lane >> 2);
            long col = n0 + wn*WN + fn*8 + (lane & 3)*2;
            float2 v0 = make_float2(d[fm][fn][0]*alpha, d[fm][fn][1]*alpha);
            float2 v1 = make_float2(d[fm][fn][2]*alpha, d[fm][fn][3]*alpha);
            if (R) {
                float2 r0 = *reinterpret_cast<const float2*>(R + row*ldc + col);
                float2 r1 = *reinterpret_cast<const float2*>(R + (row+8)*ldc + col);
                v0.x += r0.x; v0.y += r0.y; v1.x += r1.x; v1.y += r1.y;
            }
            *reinterpret_cast<float2*>(C + row*ldc + col)     = v0;
            *reinterpret_cast<float2*>(C + (row+8)*ldc + col) = v1;
        }
    }
}

// ================= host orchestration =======================================
extern "C" void kernel_launch(void* const* d_in, const int* in_sizes, int n_in,
                              void* d_out, int out_size) {
    const int*   tok     = (const int*)  d_in[0];
    const int*   pos     = (const int*)  d_in[1];
    const float* emb     = (const float*)d_in[2];
    const float* attn_nw = (const float*)d_in[3];
    const float* wq      = (const float*)d_in[4];
    const float* wk      = (const float*)d_in[5];
    const float* wv      = (const float*)d_in[6];
    const float* wo      = (const float*)d_in[7];
    const float* ff_nw   = (const float*)d_in[8];
    const float* w1      = (const float*)d_in[9];
    const float* w2      = (const float*)d_in[10];
    const float* w3      = (const float*)d_in[11];
    const float* norm_w  = (const float*)d_in[12];
    float* out = (float*)d_out;

    float *x, *q, *k, *v, *ot, *sc, *u, *t, *cb, *sb;
    cudaGetSymbolAddress((void**)&x,  g_x);
    cudaGetSymbolAddress((void**)&q,  g_q);
    cudaGetSymbolAddress((void**)&k,  g_k);
    cudaGetSymbolAddress((void**)&v,  g_v);
    cudaGetSymbolAddress((void**)&ot, g_ot);
    cudaGetSymbolAddress((void**)&sc, g_sc);
    cudaGetSymbolAddress((void**)&u,  g_u);
    cudaGetSymbolAddress((void**)&t,  g_t);
    cudaGetSymbolAddress((void**)&cb, g_cos);
    cudaGetSymbolAddress((void**)&sb, g_sin);

    __nv_bfloat16 *ah, *al, *uh, *ul, *qhh, *qhl, *khh, *khl, *vth, *vtl, *ph, *pl;
    cudaGetSymbolAddress((void**)&ah,  a_h);  cudaGetSymbolAddress((void**)&al,  a_l);
    cudaGetSymbolAddress((void**)&uh,  u_h);  cudaGetSymbolAddress((void**)&ul,  u_l);
    cudaGetSymbolAddress((void**)&qhh, qh_h); cudaGetSymbolAddress((void**)&qhl, qh_l);
    cudaGetSymbolAddress((void**)&khh, kh_h); cudaGetSymbolAddress((void**)&khl, kh_l);
    cudaGetSymbolAddress((void**)&vth, vt_h); cudaGetSymbolAddress((void**)&vtl, vt_l);
    cudaGetSymbolAddress((void**)&ph,  p_h);  cudaGetSymbolAddress((void**)&pl,  p_l);

    __nv_bfloat16 *wqh,*wql,*wkh,*wkl,*wvh,*wvl,*woh,*wol,*w1h,*w1l,*w3h,*w3l,*w2h,*w2l,*eh,*el;
    cudaGetSymbolAddress((void**)&wqh, wq_h); cudaGetSymbolAddress((void**)&wql, wq_l);
    cudaGetSymbolAddress((void**)&wkh, wk_h); cudaGetSymbolAddress((void**)&wkl, wk_l);
    cudaGetSymbolAddress((void**)&wvh, wv_h); cudaGetSymbolAddress((void**)&wvl, wv_l);
    cudaGetSymbolAddress((void**)&woh, wo_h); cudaGetSymbolAddress((void**)&wol, wo_l);
    cudaGetSymbolAddress((void**)&w1h, w1_h); cudaGetSymbolAddress((void**)&w1l, w1_l);
    cudaGetSymbolAddress((void**)&w3h, w3_h); cudaGetSymbolAddress((void**)&w3l, w3_l);
    cudaGetSymbolAddress((void**)&w2h, w2_h); cudaGetSymbolAddress((void**)&w2l, w2_l);
    cudaGetSymbolAddress((void**)&eh,  emb_h); cudaGetSymbolAddress((void**)&el,  emb_l);

    const int TPB = 256;
    // dynamic smem sizes: 2 stages of (2*A + 2*B)
    constexpr int SMEM128 = 2 * (2*128*80 + 2*128*80);   // 81920
    constexpr int SMEM64  = 2 * (2*128*80 + 2*64*80);    // 61440
    cudaFuncSetAttribute((const void*)gemm_mma_kernel<128,64,32>,
                         cudaFuncAttributeMaxDynamicSharedMemorySize, SMEM128);
    cudaFuncSetAttribute((const void*)gemm_mma_kernel<64,32,32>,
                         cudaFuncAttributeMaxDynamicSharedMemorySize, SMEM64);

    // ---- weight + embed conversion to bf16 hi/lo (vectorized) ----
    auto conv = [&](const float* s, __nv_bfloat16* dh, __nv_bfloat16* dl, long n) {
        long n4 = n >> 2;
        convert_split_kernel<<<(int)((n4 + TPB-1)/TPB), TPB>>>(s, dh, dl, n4);
    };
    conv(wq, wqh, wql, (long)LL*DD*DD);
    conv(wk, wkh, wkl, (long)LL*DD*DD);
    conv(wv, wvh, wvl, (long)LL*DD*DD);
    conv(wo, woh, wol, (long)LL*DD*DD);
    conv(w1, w1h, w1l, (long)LL*DFFN*DD);
    conv(w3, w3h, w3l, (long)LL*DFFN*DD);
    conv(w2, w2h, w2l, (long)LL*DD*DFFN);
    conv(emb, eh, el,  (long)NVOC*DD);

    embed_gather_kernel<<<(NTOK*DD/4 + TPB-1)/TPB, TPB>>>(tok, emb, x);
    rope_table_kernel<<<(NTOK*32 + TPB-1)/TPB, TPB>>>(pos, cb, sb);

    dim3 gProj(DD/128,   NTOK/128);        // (8,16)
    dim3 gFF  (DFFN/128, NTOK/128);        // (32,16)
    dim3 gHead(NVOC/128, NTOK/128);        // (128,16)
    dim3 gQK  (TT/128, TT/128, NZ);        // (8,8,32)
    dim3 gPV  (1,      TT/128, NZ);        // (1,8,32)

    for (int l = 0; l < LL; l++) {
        long woff  = (long)l*DD*DD;
        long wfoff = (long)l*DFFN*DD;

        // ---- attention ----
        rmsnorm_bf16_kernel<<<NTOK, TPB>>>(x, attn_nw + (long)l*DD, ah, al);
        gemm_mma_kernel<128,64,32><<<gProj, TPB, SMEM128>>>(
            ah, al, DD, 0, wqh+woff, wql+woff, DD, 0, q, DD, 0, nullptr, DD, 1.f);
        gemm_mma_kernel<128,64,32><<<gProj, TPB, SMEM128>>>(
            ah, al, DD, 0, wkh+woff, wkl+woff, DD, 0, k, DD, 0, nullptr, DD, 1.f);
        gemm_mma_kernel<128,64,32><<<gProj, TPB, SMEM128>>>(
            ah, al, DD, 0, wvh+woff, wvl+woff, DD, 0, v, DD, 0, nullptr, DD, 1.f);
        rope_convert_qk_kernel<<<(NTOK*HH*32 + TPB-1)/TPB, TPB>>>(q, k, cb, sb);
        vt_convert_kernel<<<(int)(((long)NZ*HDIM*TT/2 + TPB-1)/TPB), TPB>>>(v);
        gemm_mma_kernel<128,64,32><<<gQK, TPB, SMEM128>>>(
            qhh, qhl, HDIM, (long)TT*HDIM,
            khh, khl, HDIM, (long)TT*HDIM,
            sc, TT, (long)TT*TT, nullptr, HDIM, 0.125f);
        softmax_bf16_kernel<<<NZ*TT, TPB>>>(sc);
        gemm_mma_kernel<64,32,32><<<gPV, TPB, SMEM64>>>(
            ph, pl, TT, (long)TT*TT,
            vth, vtl, TT, (long)HDIM*TT,
            ot, HDIM, (long)TT*HDIM, nullptr, TT, 1.f);
        o_convert_kernel<<<(NTOK*DD/4 + TPB-1)/TPB, TPB>>>(ot);
        gemm_mma_kernel<128,64,32><<<gProj, TPB, SMEM128>>>(
            ah, al, DD, 0, woh+woff, wol+woff, DD, 0, x, DD, 0, x, DD, 1.f);

        // ---- SwiGLU FFN ----
        rmsnorm_bf16_kernel<<<NTOK, TPB>>>(x, ff_nw + (long)l*DD, ah, al);
        gemm_mma_kernel<128,64,32><<<gFF, TPB, SMEM128>>>(
            ah, al, DD, 0, w1h+wfoff, w1l+wfoff, DD, 0, u, DFFN, 0, nullptr, DD, 1.f);
        gemm_mma_kernel<128,64,32><<<gFF, TPB, SMEM128>>>(
            ah, al, DD, 0, w3h+wfoff, w3l+wfoff, DD, 0, t, DFFN, 0, nullptr, DD, 1.f);
        swiglu_bf16_kernel<<<(int)(((long)NTOK*DFFN/4 + TPB-1)/TPB), TPB>>>(u, t);
        gemm_mma_kernel<128,64,32><<<gProj, TPB, SMEM128>>>(
            uh, ul, DFFN, 0, w2h+wfoff, w2l+wfoff, DFFN, 0, x, DD, 0, x, DFFN, 1.f);
    }

    // ---- final norm + tied LM head ----
    rmsnorm_bf16_kernel<<<NTOK, TPB>>>(x, norm_w, ah, al);
    gemm_mma_kernel<128,64,32><<<gHead, TPB, SMEM128>>>(
        ah, al, DD, 0, eh, el, DD, 0, out, NVOC, 0, nullptr, DD, 1.f);
}

// round 12
// speedup vs baseline: 1.0027x; 1.0003x over previous
#include <cuda_runtime.h>
#include <cuda_bf16.h>
#include <cstdint>
#include <math.h>

// ---------------- problem constants ----------------
#define BB    2
#define TT    1024
#define DD    1024
#define HH    16
#define HDIM  64
#define LL    4
#define DFFN  4096
#define NVOC  16384
#define NTOK  (BB*TT)          // 2048
#define NZ    (BB*HH)          // 32
#define EPSS  1e-6f

// ---------------- scratch (device globals; no allocations allowed) --------
__device__ float g_x[NTOK*DD];
__device__ float g_q[NTOK*DD];
__device__ float g_k[NTOK*DD];
__device__ float g_v[NTOK*DD];
__device__ float g_ot[(long)NZ*TT*HDIM];
__device__ float g_sc[(long)NZ*TT*TT];           // 128 MB attention scores
__device__ float g_u[NTOK*DFFN];
__device__ float g_t[NTOK*DFFN];
__device__ float g_cos[NTOK*(HDIM/2)];
__device__ float g_sin[NTOK*(HDIM/2)];

// bf16 hi/lo activation buffers
__device__ __nv_bfloat16 a_h[NTOK*DD],  a_l[NTOK*DD];
__device__ __nv_bfloat16 u_h[NTOK*DFFN], u_l[NTOK*DFFN];
__device__ __nv_bfloat16 qh_h[(long)NZ*TT*HDIM], qh_l[(long)NZ*TT*HDIM];
__device__ __nv_bfloat16 kh_h[(long)NZ*TT*HDIM], kh_l[(long)NZ*TT*HDIM];
__device__ __nv_bfloat16 vt_h[(long)NZ*HDIM*TT], vt_l[(long)NZ*HDIM*TT];
__device__ __nv_bfloat16 p_h[(long)NZ*TT*TT],   p_l[(long)NZ*TT*TT];

// bf16 hi/lo weight buffers (converted each launch)
__device__ __nv_bfloat16 wq_h[LL*DD*DD],  wq_l[LL*DD*DD];
__device__ __nv_bfloat16 wk_h[LL*DD*DD],  wk_l[LL*DD*DD];
__device__ __nv_bfloat16 wv_h[LL*DD*DD],  wv_l[LL*DD*DD];
__device__ __nv_bfloat16 wo_h[LL*DD*DD],  wo_l[LL*DD*DD];
__device__ __nv_bfloat16 w1_h[(long)LL*DFFN*DD], w1_l[(long)LL*DFFN*DD];
__device__ __nv_bfloat16 w3_h[(long)LL*DFFN*DD], w3_l[(long)LL*DFFN*DD];
__device__ __nv_bfloat16 w2_h[(long)LL*DD*DFFN], w2_l[(long)LL*DD*DFFN];
__device__ __nv_bfloat16 emb_h[NVOC*DD], emb_l[NVOC*DD];

// ---------------- small helpers ----------------
__device__ __forceinline__ uint32_t smem_to_u32(const void* p) {
    uint32_t a;
    asm("{ .reg .u64 t; cvta.to.shared.u64 t, %1; cvt.u32.u64 %0, t; }"
        : "=r"(a) : "l"(p));
    return a;
}
__device__ __forceinline__ uint32_t bf16pack(float a, float b) {
    __nv_bfloat162 t = __floats2bfloat162_rn(a, b);
    return *reinterpret_cast<uint32_t*>(&t);
}
// split 4 floats -> hi uint2, lo uint2
__device__ __forceinline__ void split4(float4 v, uint2& hi, uint2& lo) {
    float h0 = __bfloat162float(__float2bfloat16(v.x));
    float h1 = __bfloat162float(__float2bfloat16(v.y));
    float h2 = __bfloat162float(__float2bfloat16(v.z));
    float h3 = __bfloat162float(__float2bfloat16(v.w));
    hi.x = bf16pack(h0, h1);          hi.y = bf16pack(h2, h3);
    lo.x = bf16pack(v.x-h0, v.y-h1);  lo.y = bf16pack(v.z-h2, v.w-h3);
}

// ================= warp MMA + cp.async helpers (sm_80+) ====================
__device__ __forceinline__ void ldsm_x4(uint32_t* r, uint32_t addr) {
    asm volatile("ldmatrix.sync.aligned.m8n8.x4.shared.b16 {%0,%1,%2,%3}, [%4];"
        : "=r"(r[0]), "=r"(r[1]), "=r"(r[2]), "=r"(r[3]) : "r"(addr));
}
__device__ __forceinline__ void ldsm_x2(uint32_t* r, uint32_t addr) {
    asm volatile("ldmatrix.sync.aligned.m8n8.x2.shared.b16 {%0,%1}, [%2];"
        : "=r"(r[0]), "=r"(r[1]) : "r"(addr));
}
__device__ __forceinline__ void mma_bf16(float* d, const uint32_t* a, const uint32_t* b) {
    asm volatile("mma.sync.aligned.m16n8k16.row.col.f32.bf16.bf16.f32 "
        "{%0,%1,%2,%3}, {%4,%5,%6,%7}, {%8,%9}, {%0,%1,%2,%3};"
        : "+f"(d[0]), "+f"(d[1]), "+f"(d[2]), "+f"(d[3])
        : "r"(a[0]), "r"(a[1]), "r"(a[2]), "r"(a[3]), "r"(b[0]), "r"(b[1]));
}
__device__ __forceinline__ void cp_async16(uint32_t dst, const void* src) {
    asm volatile("cp.async.cg.shared.global [%0], [%1], 16;" :: "r"(dst), "l"(src));
}
#define CP_COMMIT() asm volatile("cp.async.commit_group;" ::: "memory")
#define CP_WAIT1()  asm volatile("cp.async.wait_group 1;" ::: "memory")

// ================= elementwise / prep kernels ===============================
__global__ void embed_gather_kernel(const int* __restrict__ tok,
                                    const float* __restrict__ emb,
                                    float* __restrict__ x) {
    int idx = blockIdx.x * blockDim.x + threadIdx.x;     // NTOK*DD/4
    if (idx >= NTOK*DD/4) return;
    int row = idx >> 8, d4 = idx & 255;
    reinterpret_cast<float4*>(x)[idx] =
        reinterpret_cast<const float4*>(emb + (long)tok[row]*DD)[d4];
}

__global__ void rope_table_kernel(const int* __restrict__ pos,
                                  float* __restrict__ cb, float* __restrict__ sb) {
    int idx = blockIdx.x * blockDim.x + threadIdx.x;
    if (idx >= NTOK*(HDIM/2)) return;
    int row = idx >> 5, i = idx & 31;
    double inv = exp(-((double)(2*i) / (double)HDIM) * log(10000.0));
    double ang = (double)pos[row] * inv;
    cb[idx] = (float)cos(ang);
    sb[idx] = (float)sin(ang);
}

__global__ void convert_split_kernel(const float* __restrict__ src,
                                     __nv_bfloat16* __restrict__ dh,
                                     __nv_bfloat16* __restrict__ dl, long n4) {
    long idx = (long)blockIdx.x * blockDim.x + threadIdx.x;
    if (idx >= n4) return;
    float4 v = reinterpret_cast<const float4*>(src)[idx];
    uint2 hi, lo; split4(v, hi, lo);
    reinterpret_cast<uint2*>(dh)[idx] = hi;
    reinterpret_cast<uint2*>(dl)[idx] = lo;
}

__global__ void rmsnorm_bf16_kernel(const float* __restrict__ x,
                                    const float* __restrict__ w,
                                    __nv_bfloat16* __restrict__ oh,
                                    __nv_bfloat16* __restrict__ ol) {
    int row = blockIdx.x;
    int tid = threadIdx.x;
    const float4* xr = reinterpret_cast<const float4*>(x + (long)row*DD);
    float4 v = xr[tid];
    __shared__ float red[256];
    float s = v.x*v.x + v.y*v.y + v.z*v.z + v.w*v.w;
    red[tid] = s; __syncthreads();
    for (int off = 128; off > 0; off >>= 1) {
        if (tid < off) red[tid] += red[tid + off];
        __syncthreads();
    }
    float inv = rsqrtf(red[0] / (float)DD + EPSS);
    float4 wv = reinterpret_cast<const float4*>(w)[tid];
    float4 o = make_float4(v.x*inv*wv.x, v.y*inv*wv.y, v.z*inv*wv.z, v.w*inv*wv.w);
    uint2 hi, lo; split4(o, hi, lo);
    reinterpret_cast<uint2*>(oh + (long)row*DD)[tid] = hi;
    reinterpret_cast<uint2*>(ol + (long)row*DD)[tid] = lo;
}

// rope + reshape to head layout [z][t][64] (hi/lo)
__global__ void rope_convert_qk_kernel(const float* __restrict__ q,
                                       const float* __restrict__ k,
                                       const float* __restrict__ cb,
                                       const float* __restrict__ sb) {
    int idx = blockIdx.x * blockDim.x + threadIdx.x;
    if (idx >= NTOK*HH*32) return;
    int row = idx >> 9, rem = idx & 511, h = rem >> 5, i = rem & 31;
    float c = cb[row*32 + i], s = sb[row*32 + i];
    int b = row >> 10, t = row & 1023;
    long src = (long)row*DD + h*HDIM + 2*i;
    long dst = ((long)(b*HH + h) * TT + t) * HDIM + 2*i;
    float2 qv = *reinterpret_cast<const float2*>(q + src);
    float2 kv = *reinterpret_cast<const float2*>(k + src);
    float q0 = qv.x*c - qv.y*s, q1 = qv.x*s + qv.y*c;
    float k0 = kv.x*c - kv.y*s, k1 = kv.x*s + kv.y*c;
    float q0h = __bfloat162float(__float2bfloat16(q0));
    float q1h = __bfloat162float(__float2bfloat16(q1));
    float k0h = __bfloat162float(__float2bfloat16(k0));
    float k1h = __bfloat162float(__float2bfloat16(k1));
    *reinterpret_cast<uint32_t*>(&qh_h[dst]) = bf16pack(q0h, q1h);
    *reinterpret_cast<uint32_t*>(&qh_l[dst]) = bf16pack(q0-q0h, q1-q1h);
    *reinterpret_cast<uint32_t*>(&kh_h[dst]) = bf16pack(k0h, k1h);
    *reinterpret_cast<uint32_t*>(&kh_l[dst]) = bf16pack(k0-k0h, k1-k1h);
}

// V -> Vt [z][hd][s] hi/lo (transposed for PV B-operand); 2 s-elems per thread
__global__ void vt_convert_kernel(const float* __restrict__ v) {
    long idx2 = (long)blockIdx.x * blockDim.x + threadIdx.x;   // NZ*HDIM*TT/2
    if (idx2 >= (long)NZ*HDIM*TT/2) return;
    long idx = idx2 * 2;
    int z = (int)(idx >> 16);
    int rem = (int)(idx & 65535);
    int hd = rem >> 10, s = rem & 1023;
    int b = z >> 4, h = z & 15;
    float v0 = v[((long)b*TT + s  )*DD + h*HDIM + hd];
    float v1 = v[((long)b*TT + s+1)*DD + h*HDIM + hd];
    float h0 = __bfloat162float(__float2bfloat16(v0));
    float h1 = __bfloat162float(__float2bfloat16(v1));
    *reinterpret_cast<uint32_t*>(&vt_h[idx]) = bf16pack(h0, h1);
    *reinterpret_cast<uint32_t*>(&vt_l[idx]) = bf16pack(v0-h0, v1-h1);
}

// o [z][t][64] -> a_h/a_l [b*T+t][D]; 4 elems per thread
__global__ void o_convert_kernel(const float* __restrict__ ot) {
    int idx = blockIdx.x * blockDim.x + threadIdx.x;     // NTOK*DD/4
    if (idx >= NTOK*DD/4) return;
    int row = idx >> 8, c4 = (idx & 255) * 4;
    int h = c4 >> 6, hd = c4 & 63;
    int b = row >> 10, t = row & 1023;
    float4 v = *reinterpret_cast<const float4*>(
        ot + ((long)(b*HH + h)*TT + t)*HDIM + hd);
    uint2 hi, lo; split4(v, hi, lo);
    reinterpret_cast<uint2*>(a_h)[idx] = hi;
    reinterpret_cast<uint2*>(a_l)[idx] = lo;
}

__global__ void softmax_bf16_kernel(const float* __restrict__ sc) {
    long row = blockIdx.x;
    int tid = threadIdx.x;
    float4 v = reinterpret_cast<const float4*>(sc + row*TT)[tid];
    __shared__ float red[256];
    float m = fmaxf(fmaxf(v.x, v.y), fmaxf(v.z, v.w));
    red[tid] = m; __syncthreads();
    for (int off = 128; off > 0; off >>= 1) {
        if (tid < off) red[tid] = fmaxf(red[tid], red[tid+off]);
        __syncthreads();
    }
    m = red[0]; __syncthreads();
    v.x = expf(v.x - m); v.y = expf(v.y - m);
    v.z = expf(v.z - m); v.w = expf(v.w - m);
    red[tid] = v.x + v.y + v.z + v.w; __syncthreads();
    for (int off = 128; off > 0; off >>= 1) {
        if (tid < off) red[tid] += red[tid+off];
        __syncthreads();
    }
    float inv = 1.f / red[0];
    v.x *= inv; v.y *= inv; v.z *= inv; v.w *= inv;
    uint2 hi, lo; split4(v, hi, lo);
    reinterpret_cast<uint2*>(p_h + row*TT)[tid] = hi;
    reinterpret_cast<uint2*>(p_l + row*TT)[tid] = lo;
}

__global__ void swiglu_bf16_kernel(const float* __restrict__ u,
                                   const float* __restrict__ t) {
    long idx = (long)blockIdx.x * blockDim.x + threadIdx.x;   // NTOK*DFFN/4
    if (idx >= (long)NTOK*DFFN/4) return;
    float4 uv = reinterpret_cast<const float4*>(u)[idx];
    float4 tv = reinterpret_cast<const float4*>(t)[idx];
    float4 g;
    g.x = uv.x / (1.f + expf(-uv.x)) * tv.x;
    g.y = uv.y / (1.f + expf(-uv.y)) * tv.y;
    g.z = uv.z / (1.f + expf(-uv.z)) * tv.z;
    g.w = uv.w / (1.f + expf(-uv.w)) * tv.w;
    uint2 hi, lo; split4(g, hi, lo);
    reinterpret_cast<uint2*>(u_h)[idx] = hi;
    reinterpret_cast<uint2*>(u_l)[idx] = lo;
}

// ================= bf16x3 GEMM via mma.sync + cp.async pipeline =============
// C[M,N](+z) = alpha * A[M,K] * B[N,K]^T (+ Res), 3-term bf16 split.
// BM=128, BK=32 per stage, 2-stage cp.async double buffer. 256 thr = 8 warps.
// SMEM rows padded to 80B (5x16B) -> conflict-free ldmatrix phases.
template<int BN, int WM, int WN>
__global__ void __launch_bounds__(256, 2)
gemm_mma_kernel(const __nv_bfloat16* __restrict__ Ah,
                const __nv_bfloat16* __restrict__ Al, long lda, long strideAz,
                const __nv_bfloat16* __restrict__ Bh,
                const __nv_bfloat16* __restrict__ Bl, long ldb, long strideBz,
                float* __restrict__ C, long ldc, long strideCz,
                const float* __restrict__ Res,
                int K, float alpha)
{
    constexpr int BM = 128;
    constexpr int MF = WM / 16;
    constexpr int NF = WN / 8;
    constexpr int WMS = BM / WM;
    constexpr int ROWB = 80;
    constexpr int ASZ = BM * ROWB;          // per-term A bytes
    constexpr int BSZ = BN * ROWB;
    constexpr int STAGE = 2*ASZ + 2*BSZ;

    extern __shared__ char smem[];
    const uint32_t s0 = smem_to_u32(smem);

    int tid = threadIdx.x, wid = tid >> 5, lane = tid & 31;
    int wm = wid % WMS, wn = wid / WMS;
    int z = blockIdx.z;
    Ah += (long)z * strideAz;  Al += (long)z * strideAz;
    Bh += (long)z * strideBz;  Bl += (long)z * strideBz;
    C  += (long)z * strideCz;
    const float* R = Res ? Res + (long)z * strideCz : nullptr;

    const int m0 = blockIdx.y * BM;
    const int n0 = blockIdx.x * BN;

    // prefetch lambda: stage buffer `st`, k offset k0
    auto prefetch = [&](int st, int k0) {
        uint32_t sb = s0 + st * STAGE;
        #pragma unroll
        for (int i = tid; i < BM*8; i += 256) {          // A: 2 terms x 128 x 4
            int term = i >> 9, rem = i & 511;
            int r = rem >> 2, c = rem & 3;
            const __nv_bfloat16* src = (term ? Al : Ah) + (long)(m0 + r)*lda + k0 + c*8;
            cp_async16(sb + term*ASZ + r*ROWB + c*16, src);
        }
        #pragma unroll
        for (int i = tid; i < BN*8; i += 256) {          // B: 2 terms x BN x 4
            int term = i >= BN*4;
            int rem = term ? i - BN*4 : i;
            int r = rem >> 2, c = rem & 3;
            const __nv_bfloat16* src = (term ? Bl : Bh) + (long)(n0 + r)*ldb + k0 + c*8;
            cp_async16(sb + 2*ASZ + term*BSZ + r*ROWB + c*16, src);
        }
    };

    float d[MF][NF][4] = {};
    const int lm16 = lane & 15, lq = lane >> 4;
    const int lb8  = lane & 7,  lh = (lane >> 3) & 1;

    const int nsteps = K >> 5;
    prefetch(0, 0);
    CP_COMMIT();

    for (int s = 0; s < nsteps; s++) {
        if (s + 1 < nsteps) prefetch((s + 1) & 1, (s + 1) << 5);
        CP_COMMIT();
        CP_WAIT1();
        __syncthreads();

        uint32_t sb  = s0 + (s & 1) * STAGE;
        uint32_t sAh = sb, sAl = sb + ASZ;
        uint32_t sBh = sb + 2*ASZ, sBl = sb + 2*ASZ + BSZ;

        #pragma unroll
        for (int kk = 0; kk < 32; kk += 16) {
            uint32_t ah[MF][4], al[MF][4];
            #pragma unroll
            for (int fm = 0; fm < MF; fm++) {
                uint32_t off = (uint32_t)((wm*WM + fm*16 + lm16)*ROWB + (kk + lq*8)*2);
                ldsm_x4(ah[fm], sAh + off);
                ldsm_x4(al[fm], sAl + off);
            }
            #pragma unroll
            for (int fn = 0; fn < NF; fn++) {
                uint32_t bh[2], bl[2];
                uint32_t off = (uint32_t)((wn*WN + fn*8 + lb8)*ROWB + (kk + lh*8)*2);
                ldsm_x2(bh, sBh + off);
                ldsm_x2(bl, sBl + off);
                #pragma unroll
                for (int fm = 0; fm < MF; fm++) {
                    mma_bf16(d[fm][fn], ah[fm], bh);
                    mma_bf16(d[fm][fn], ah[fm], bl);
                    mma_bf16(d[fm][fn], al[fm], bh);
                }
            }
        }
        __syncthreads();
    }

    // ---- epilogue: alpha scale + optional residual ----
    #pragma unroll
    for (int fm = 0; fm < MF; fm++) {
        #pragma unroll
        for (int fn = 0; fn < NF; fn++) {
            long row = m0 + wm*WM + fm*16 + (lane >> 2);
            long col = n0 + wn*WN + fn*8 + (lane & 3)*2;
            float2 v0 = make_float2(d[fm][fn][0]*alpha, d[fm][fn][1]*alpha);
            float2 v1 = make_float2(d[fm][fn][2]*alpha, d[fm][fn][3]*alpha);
            if (R) {
                float2 r0 = *reinterpret_cast<const float2*>(R + row*ldc + col);
                float2 r1 = *reinterpret_cast<const float2*>(R + (row+8)*ldc + col);
                v0.x += r0.x; v0.y += r0.y; v1.x += r1.x; v1.y += r1.y;
            }
            *reinterpret_cast<float2*>(C + row*ldc + col)     = v0;
            *reinterpret_cast<float2*>(C + (row+8)*ldc + col) = v1;
        }
    }
}

// ================= host orchestration =======================================
extern "C" void kernel_launch(void* const* d_in, const int* in_sizes, int n_in,
                              void* d_out, int out_size) {
    const int*   tok     = (const int*)  d_in[0];
    const int*   pos     = (const int*)  d_in[1];
    const float* emb     = (const float*)d_in[2];
    const float* attn_nw = (const float*)d_in[3];
    const float* wq      = (const float*)d_in[4];
    const float* wk      = (const float*)d_in[5];
    const float* wv      = (const float*)d_in[6];
    const float* wo      = (const float*)d_in[7];
    const float* ff_nw   = (const float*)d_in[8];
    const float* w1      = (const float*)d_in[9];
    const float* w2      = (const float*)d_in[10];
    const float* w3      = (const float*)d_in[11];
    const float* norm_w  = (const float*)d_in[12];
    float* out = (float*)d_out;

    float *x, *q, *k, *v, *ot, *sc, *u, *t, *cb, *sb;
    cudaGetSymbolAddress((void**)&x,  g_x);
    cudaGetSymbolAddress((void**)&q,  g_q);
    cudaGetSymbolAddress((void**)&k,  g_k);
    cudaGetSymbolAddress((void**)&v,  g_v);
    cudaGetSymbolAddress((void**)&ot, g_ot);
    cudaGetSymbolAddress((void**)&sc, g_sc);
    cudaGetSymbolAddress((void**)&u,  g_u);
    cudaGetSymbolAddress((void**)&t,  g_t);
    cudaGetSymbolAddress((void**)&cb, g_cos);
    cudaGetSymbolAddress((void**)&sb, g_sin);

    __nv_bfloat16 *ah, *al, *uh, *ul, *qhh, *qhl, *khh, *khl, *vth, *vtl, *ph, *pl;
    cudaGetSymbolAddress((void**)&ah,  a_h);  cudaGetSymbolAddress((void**)&al,  a_l);
    cudaGetSymbolAddress((void**)&uh,  u_h);  cudaGetSymbolAddress((void**)&ul,  u_l);
    cudaGetSymbolAddress((void**)&qhh, qh_h); cudaGetSymbolAddress((void**)&qhl, qh_l);
    cudaGetSymbolAddress((void**)&khh, kh_h); cudaGetSymbolAddress((void**)&khl, kh_l);
    cudaGetSymbolAddress((void**)&vth, vt_h); cudaGetSymbolAddress((void**)&vtl, vt_l);
    cudaGetSymbolAddress((void**)&ph,  p_h);  cudaGetSymbolAddress((void**)&pl,  p_l);

    __nv_bfloat16 *wqh,*wql,*wkh,*wkl,*wvh,*wvl,*woh,*wol,*w1h,*w1l,*w3h,*w3l,*w2h,*w2l,*eh,*el;
    cudaGetSymbolAddress((void**)&wqh, wq_h); cudaGetSymbolAddress((void**)&wql, wq_l);
    cudaGetSymbolAddress((void**)&wkh, wk_h); cudaGetSymbolAddress((void**)&wkl, wk_l);
    cudaGetSymbolAddress((void**)&wvh, wv_h); cudaGetSymbolAddress((void**)&wvl, wv_l);
    cudaGetSymbolAddress((void**)&woh, wo_h); cudaGetSymbolAddress((void**)&wol, wo_l);
    cudaGetSymbolAddress((void**)&w1h, w1_h); cudaGetSymbolAddress((void**)&w1l, w1_l);
    cudaGetSymbolAddress((void**)&w3h, w3_h); cudaGetSymbolAddress((void**)&w3l, w3_l);
    cudaGetSymbolAddress((void**)&w2h, w2_h); cudaGetSymbolAddress((void**)&w2l, w2_l);
    cudaGetSymbolAddress((void**)&eh,  emb_h); cudaGetSymbolAddress((void**)&el,  emb_l);

    const int TPB = 256;
    // dynamic smem sizes: 2 stages of (2*A + 2*B)
    constexpr int SMEM128 = 2 * (2*128*80 + 2*128*80);   // 81920
    constexpr int SMEM64  = 2 * (2*128*80 + 2*64*80);    // 61440
    cudaFuncSetAttribute((const void*)gemm_mma_kernel<128,64,32>,
                         cudaFuncAttributeMaxDynamicSharedMemorySize, SMEM128);
    cudaFuncSetAttribute((const void*)gemm_mma_kernel<64,32,32>,
                         cudaFuncAttributeMaxDynamicSharedMemorySize, SMEM64);

    // ---- weight + embed conversion to bf16 hi/lo (vectorized) ----
    auto conv = [&](const float* s, __nv_bfloat16* dh, __nv_bfloat16* dl, long n) {
        long n4 = n >> 2;
        convert_split_kernel<<<(int)((n4 + TPB-1)/TPB), TPB>>>(s, dh, dl, n4);
    };
    conv(wq, wqh, wql, (long)LL*DD*DD);
    conv(wk, wkh, wkl, (long)LL*DD*DD);
    conv(wv, wvh, wvl, (long)LL*DD*DD);
    conv(wo, woh, wol, (long)LL*DD*DD);
    conv(w1, w1h, w1l, (long)LL*DFFN*DD);
    conv(w3, w3h, w3l, (long)LL*DFFN*DD);
    conv(w2, w2h, w2l, (long)LL*DD*DFFN);
    conv(emb, eh, el,  (long)NVOC*DD);

    embed_gather_kernel<<<(NTOK*DD/4 + TPB-1)/TPB, TPB>>>(tok, emb, x);
    rope_table_kernel<<<(NTOK*32 + TPB-1)/TPB, TPB>>>(pos, cb, sb);

    dim3 gProj(DD/128,   NTOK/128);        // (8,16)
    dim3 gFF  (DFFN/128, NTOK/128);        // (32,16)
    dim3 gHead(NVOC/128, NTOK/128);        // (128,16)
    dim3 gQK  (TT/128, TT/128, NZ);        // (8,8,32)
    dim3 gPV  (1,      TT/128, NZ);        // (1,8,32)

    for (int l = 0; l < LL; l++) {
        long woff  = (long)l*DD*DD;
        long wfoff = (long)l*DFFN*DD;

        // ---- attention ----
        rmsnorm_bf16_kernel<<<NTOK, TPB>>>(x, attn_nw + (long)l*DD, ah, al);
        gemm_mma_kernel<128,64,32><<<gProj, TPB, SMEM128>>>(
            ah, al, DD, 0, wqh+woff, wql+woff, DD, 0, q, DD, 0, nullptr, DD, 1.f);
        gemm_mma_kernel<128,64,32><<<gProj, TPB, SMEM128>>>(
            ah, al, DD, 0, wkh+woff, wkl+woff, DD, 0, k, DD, 0, nullptr, DD, 1.f);
        gemm_mma_kernel<128,64,32><<<gProj, TPB, SMEM128>>>(
            ah, al, DD, 0, wvh+woff, wvl+woff, DD, 0, v, DD, 0, nullptr, DD, 1.f);
        rope_convert_qk_kernel<<<(NTOK*HH*32 + TPB-1)/TPB, TPB>>>(q, k, cb, sb);
        vt_convert_kernel<<<(int)(((long)NZ*HDIM*TT/2 + TPB-1)/TPB), TPB>>>(v);
        gemm_mma_kernel<128,64,32><<<gQK, TPB, SMEM128>>>(
            qhh, qhl, HDIM, (long)TT*HDIM,
            khh, khl, HDIM, (long)TT*HDIM,
            sc, TT, (long)TT*TT, nullptr, HDIM, 0.125f);
        softmax_bf16_kernel<<<NZ*TT, TPB>>>(sc);
        gemm_mma_kernel<64,32,32><<<gPV, TPB, SMEM64>>>(
            ph, pl, TT, (long)TT*TT,
            vth, vtl, TT, (long)HDIM*TT,
            ot, HDIM, (long)TT*HDIM, nullptr, TT, 1.f);
        o_convert_kernel<<<(NTOK*DD/4 + TPB-1)/TPB, TPB>>>(ot);
        gemm_mma_kernel<128,64,32><<<gProj, TPB, SMEM128>>>(
            ah, al, DD, 0, woh+woff, wol+woff, DD, 0, x, DD, 0, x, DD, 1.f);

        // ---- SwiGLU FFN ----
        rmsnorm_bf16_kernel<<<NTOK, TPB>>>(x, ff_nw + (long)l*DD, ah, al);
        gemm_mma_kernel<128,64,32><<<gFF, TPB, SMEM128>>>(
            ah, al, DD, 0, w1h+wfoff, w1l+wfoff, DD, 0, u, DFFN, 0, nullptr, DD, 1.f);
        gemm_mma_kernel<128,64,32><<<gFF, TPB, SMEM128>>>(
            ah, al, DD, 0, w3h+wfoff, w3l+wfoff, DD, 0, t, DFFN, 0, nullptr, DD, 1.f);
        swiglu_bf16_kernel<<<(int)(((long)NTOK*DFFN/4 + TPB-1)/TPB), TPB>>>(u, t);
        gemm_mma_kernel<128,64,32><<<gProj, TPB, SMEM128>>>(
            uh, ul, DFFN, 0, w2h+wfoff, w2l+wfoff, DFFN, 0, x, DD, 0, x, DFFN, 1.f);
    }

    // ---- final norm + tied LM head ----
    rmsnorm_bf16_kernel<<<NTOK, TPB>>>(x, norm_w, ah, al);
    gemm_mma_kernel<128,64,32><<<gHead, TPB, SMEM128>>>(
        ah, al, DD, 0, eh, el, DD, 0, out, NVOC, 0, nullptr, DD, 1.f);
}

// round 13
// speedup vs baseline: 1.0027x; 1.0000x over previous
#include <cuda_runtime.h>
#include <cuda_bf16.h>
#include <cstdint>
#include <math.h>

// ---------------- problem constants ----------------
#define BB    2
#define TT    1024
#define DD    1024
#define HH    16
#define HDIM  64
#define LL    4
#define DFFN  4096
#define NVOC  16384
#define NTOK  (BB*TT)          // 2048
#define NZ    (BB*HH)          // 32
#define EPSS  1e-6f

// ---------------- scratch (device globals; no allocations allowed) --------
__device__ float g_x[NTOK*DD];
__device__ float g_q[NTOK*DD];
__device__ float g_k[NTOK*DD];
__device__ float g_v[NTOK*DD];
__device__ float g_ot[(long)NZ*TT*HDIM];
__device__ float g_sc[(long)NZ*TT*TT];           // 128 MB attention scores
__device__ float g_u[NTOK*DFFN];
__device__ float g_t[NTOK*DFFN];
__device__ float g_cos[NTOK*(HDIM/2)];
__device__ float g_sin[NTOK*(HDIM/2)];

// bf16 hi/lo activation buffers
__device__ __nv_bfloat16 a_h[NTOK*DD],  a_l[NTOK*DD];
__device__ __nv_bfloat16 u_h[NTOK*DFFN], u_l[NTOK*DFFN];
__device__ __nv_bfloat16 qh_h[(long)NZ*TT*HDIM], qh_l[(long)NZ*TT*HDIM];
__device__ __nv_bfloat16 kh_h[(long)NZ*TT*HDIM], kh_l[(long)NZ*TT*HDIM];
__device__ __nv_bfloat16 vt_h[(long)NZ*HDIM*TT], vt_l[(long)NZ*HDIM*TT];
__device__ __nv_bfloat16 p_h[(long)NZ*TT*TT],   p_l[(long)NZ*TT*TT];

// bf16 hi/lo weight buffers (converted each launch)
__device__ __nv_bfloat16 wq_h[LL*DD*DD],  wq_l[LL*DD*DD];
__device__ __nv_bfloat16 wk_h[LL*DD*DD],  wk_l[LL*DD*DD];
__device__ __nv_bfloat16 wv_h[LL*DD*DD],  wv_l[LL*DD*DD];
__device__ __nv_bfloat16 wo_h[LL*DD*DD],  wo_l[LL*DD*DD];
__device__ __nv_bfloat16 w1_h[(long)LL*DFFN*DD], w1_l[(long)LL*DFFN*DD];
__device__ __nv_bfloat16 w3_h[(long)LL*DFFN*DD], w3_l[(long)LL*DFFN*DD];
__device__ __nv_bfloat16 w2_h[(long)LL*DD*DFFN], w2_l[(long)LL*DD*DFFN];
__device__ __nv_bfloat16 emb_h[NVOC*DD], emb_l[NVOC*DD];

// ---------------- small helpers ----------------
__device__ __forceinline__ uint32_t smem_to_u32(const void* p) {
    uint32_t a;
    asm("{ .reg .u64 t; cvta.to.shared.u64 t, %1; cvt.u32.u64 %0, t; }"
        : "=r"(a) : "l"(p));
    return a;
}
__device__ __forceinline__ uint32_t bf16pack(float a, float b) {
    __nv_bfloat162 t = __floats2bfloat162_rn(a, b);
    return *reinterpret_cast<uint32_t*>(&t);
}
// split 4 floats -> hi uint2, lo uint2
__device__ __forceinline__ void split4(float4 v, uint2& hi, uint2& lo) {
    float h0 = __bfloat162float(__float2bfloat16(v.x));
    float h1 = __bfloat162float(__float2bfloat16(v.y));
    float h2 = __bfloat162float(__float2bfloat16(v.z));
    float h3 = __bfloat162float(__float2bfloat16(v.w));
    hi.x = bf16pack(h0, h1);          hi.y = bf16pack(h2, h3);
    lo.x = bf16pack(v.x-h0, v.y-h1);  lo.y = bf16pack(v.z-h2, v.w-h3);
}

// ================= warp MMA + cp.async helpers (sm_80+) ====================
__device__ __forceinline__ void ldsm_x4(uint32_t* r, uint32_t addr) {
    asm volatile("ldmatrix.sync.aligned.m8n8.x4.shared.b16 {%0,%1,%2,%3}, [%4];"
        : "=r"(r[0]), "=r"(r[1]), "=r"(r[2]), "=r"(r[3]) : "r"(addr));
}
__device__ __forceinline__ void ldsm_x2(uint32_t* r, uint32_t addr) {
    asm volatile("ldmatrix.sync.aligned.m8n8.x2.shared.b16 {%0,%1}, [%2];"
        : "=r"(r[0]), "=r"(r[1]) : "r"(addr));
}
__device__ __forceinline__ void mma_bf16(float* d, const uint32_t* a, const uint32_t* b) {
    asm volatile("mma.sync.aligned.m16n8k16.row.col.f32.bf16.bf16.f32 "
        "{%0,%1,%2,%3}, {%4,%5,%6,%7}, {%8,%9}, {%0,%1,%2,%3};"
        : "+f"(d[0]), "+f"(d[1]), "+f"(d[2]), "+f"(d[3])
        : "r"(a[0]), "r"(a[1]), "r"(a[2]), "r"(a[3]), "r"(b[0]), "r"(b[1]));
}
__device__ __forceinline__ void cp_async16(uint32_t dst, const void* src) {
    asm volatile("cp.async.cg.shared.global [%0], [%1], 16;" :: "r"(dst), "l"(src));
}
#define CP_COMMIT() asm volatile("cp.async.commit_group;" ::: "memory")
#define CP_WAIT1()  asm volatile("cp.async.wait_group 1;" ::: "memory")

// ================= elementwise / prep kernels ===============================
__global__ void embed_gather_kernel(const int* __restrict__ tok,
                                    const float* __restrict__ emb,
                                    float* __restrict__ x) {
    int idx = blockIdx.x * blockDim.x + threadIdx.x;     // NTOK*DD/4
    if (idx >= NTOK*DD/4) return;
    int row = idx >> 8, d4 = idx & 255;
    reinterpret_cast<float4*>(x)[idx] =
        reinterpret_cast<const float4*>(emb + (long)tok[row]*DD)[d4];
}

__global__ void rope_table_kernel(const int* __restrict__ pos,
                                  float* __restrict__ cb, float* __restrict__ sb) {
    int idx = blockIdx.x * blockDim.x + threadIdx.x;
    if (idx >= NTOK*(HDIM/2)) return;
    int row = idx >> 5, i = idx & 31;
    double inv = exp(-((double)(2*i) / (double)HDIM) * log(10000.0));
    double ang = (double)pos[row] * inv;
    cb[idx] = (float)cos(ang);
    sb[idx] = (float)sin(ang);
}

__global__ void convert_split_kernel(const float* __restrict__ src,
                                     __nv_bfloat16* __restrict__ dh,
                                     __nv_bfloat16* __restrict__ dl, long n4) {
    long idx = (long)blockIdx.x * blockDim.x + threadIdx.x;
    if (idx >= n4) return;
    float4 v = reinterpret_cast<const float4*>(src)[idx];
    uint2 hi, lo; split4(v, hi, lo);
    reinterpret_cast<uint2*>(dh)[idx] = hi;
    reinterpret_cast<uint2*>(dl)[idx] = lo;
}

__global__ void rmsnorm_bf16_kernel(const float* __restrict__ x,
                                    const float* __restrict__ w,
                                    __nv_bfloat16* __restrict__ oh,
                                    __nv_bfloat16* __restrict__ ol) {
    int row = blockIdx.x;
    int tid = threadIdx.x;
    const float4* xr = reinterpret_cast<const float4*>(x + (long)row*DD);
    float4 v = xr[tid];
    __shared__ float red[256];
    float s = v.x*v.x + v.y*v.y + v.z*v.z + v.w*v.w;
    red[tid] = s; __syncthreads();
    for (int off = 128; off > 0; off >>= 1) {
        if (tid < off) red[tid] += red[tid + off];
        __syncthreads();
    }
    float inv = rsqrtf(red[0] / (float)DD + EPSS);
    float4 wv = reinterpret_cast<const float4*>(w)[tid];
    float4 o = make_float4(v.x*inv*wv.x, v.y*inv*wv.y, v.z*inv*wv.z, v.w*inv*wv.w);
    uint2 hi, lo; split4(o, hi, lo);
    reinterpret_cast<uint2*>(oh + (long)row*DD)[tid] = hi;
    reinterpret_cast<uint2*>(ol + (long)row*DD)[tid] = lo;
}

// rope + reshape to head layout [z][t][64] (hi/lo)
__global__ void rope_convert_qk_kernel(const float* __restrict__ q,
                                       const float* __restrict__ k,
                                       const float* __restrict__ cb,
                                       const float* __restrict__ sb) {
    int idx = blockIdx.x * blockDim.x + threadIdx.x;
    if (idx >= NTOK*HH*32) return;
    int row = idx >> 9, rem = idx & 511, h = rem >> 5, i = rem & 31;
    float c = cb[row*32 + i], s = sb[row*32 + i];
    int b = row >> 10, t = row & 1023;
    long src = (long)row*DD + h*HDIM + 2*i;
    long dst = ((long)(b*HH + h) * TT + t) * HDIM + 2*i;
    float2 qv = *reinterpret_cast<const float2*>(q + src);
    float2 kv = *reinterpret_cast<const float2*>(k + src);
    float q0 = qv.x*c - qv.y*s, q1 = qv.x*s + qv.y*c;
    float k0 = kv.x*c - kv.y*s, k1 = kv.x*s + kv.y*c;
    float q0h = __bfloat162float(__float2bfloat16(q0));
    float q1h = __bfloat162float(__float2bfloat16(q1));
    float k0h = __bfloat162float(__float2bfloat16(k0));
    float k1h = __bfloat162float(__float2bfloat16(k1));
    *reinterpret_cast<uint32_t*>(&qh_h[dst]) = bf16pack(q0h, q1h);
    *reinterpret_cast<uint32_t*>(&qh_l[dst]) = bf16pack(q0-q0h, q1-q1h);
    *reinterpret_cast<uint32_t*>(&kh_h[dst]) = bf16pack(k0h, k1h);
    *reinterpret_cast<uint32_t*>(&kh_l[dst]) = bf16pack(k0-k0h, k1-k1h);
}

// V -> Vt [z][hd][s] hi/lo (transposed for PV B-operand); 2 s-elems per thread
__global__ void vt_convert_kernel(const float* __restrict__ v) {
    long idx2 = (long)blockIdx.x * blockDim.x + threadIdx.x;   // NZ*HDIM*TT/2
    if (idx2 >= (long)NZ*HDIM*TT/2) return;
    long idx = idx2 * 2;
    int z = (int)(idx >> 16);
    int rem = (int)(idx & 65535);
    int hd = rem >> 10, s = rem & 1023;
    int b = z >> 4, h = z & 15;
    float v0 = v[((long)b*TT + s  )*DD + h*HDIM + hd];
    float v1 = v[((long)b*TT + s+1)*DD + h*HDIM + hd];
    float h0 = __bfloat162float(__float2bfloat16(v0));
    float h1 = __bfloat162float(__float2bfloat16(v1));
    *reinterpret_cast<uint32_t*>(&vt_h[idx]) = bf16pack(h0, h1);
    *reinterpret_cast<uint32_t*>(&vt_l[idx]) = bf16pack(v0-h0, v1-h1);
}

// o [z][t][64] -> a_h/a_l [b*T+t][D]; 4 elems per thread
__global__ void o_convert_kernel(const float* __restrict__ ot) {
    int idx = blockIdx.x * blockDim.x + threadIdx.x;     // NTOK*DD/4
    if (idx >= NTOK*DD/4) return;
    int row = idx >> 8, c4 = (idx & 255) * 4;
    int h = c4 >> 6, hd = c4 & 63;
    int b = row >> 10, t = row & 1023;
    float4 v = *reinterpret_cast<const float4*>(
        ot + ((long)(b*HH + h)*TT + t)*HDIM + hd);
    uint2 hi, lo; split4(v, hi, lo);
    reinterpret_cast<uint2*>(a_h)[idx] = hi;
    reinterpret_cast<uint2*>(a_l)[idx] = lo;
}

__global__ void softmax_bf16_kernel(const float* __restrict__ sc) {
    long row = blockIdx.x;
    int tid = threadIdx.x;
    float4 v = reinterpret_cast<const float4*>(sc + row*TT)[tid];
    __shared__ float red[256];
    float m = fmaxf(fmaxf(v.x, v.y), fmaxf(v.z, v.w));
    red[tid] = m; __syncthreads();
    for (int off = 128; off > 0; off >>= 1) {
        if (tid < off) red[tid] = fmaxf(red[tid], red[tid+off]);
        __syncthreads();
    }
    m = red[0]; __syncthreads();
    v.x = expf(v.x - m); v.y = expf(v.y - m);
    v.z = expf(v.z - m); v.w = expf(v.w - m);
    red[tid] = v.x + v.y + v.z + v.w; __syncthreads();
    for (int off = 128; off > 0; off >>= 1) {
        if (tid < off) red[tid] += red[tid+off];
        __syncthreads();
    }
    float inv = 1.f / red[0];
    v.x *= inv; v.y *= inv; v.z *= inv; v.w *= inv;
    uint2 hi, lo; split4(v, hi, lo);
    reinterpret_cast<uint2*>(p_h + row*TT)[tid] = hi;
    reinterpret_cast<uint2*>(p_l + row*TT)[tid] = lo;
}

__global__ void swiglu_bf16_kernel(const float* __restrict__ u,
                                   const float* __restrict__ t) {
    long idx = (long)blockIdx.x * blockDim.x + threadIdx.x;   // NTOK*DFFN/4
    if (idx >= (long)NTOK*DFFN/4) return;
    float4 uv = reinterpret_cast<const float4*>(u)[idx];
    float4 tv = reinterpret_cast<const float4*>(t)[idx];
    float4 g;
    g.x = uv.x / (1.f + expf(-uv.x)) * tv.x;
    g.y = uv.y / (1.f + expf(-uv.y)) * tv.y;
    g.z = uv.z / (1.f + expf(-uv.z)) * tv.z;
    g.w = uv.w / (1.f + expf(-uv.w)) * tv.w;
    uint2 hi, lo; split4(g, hi, lo);
    reinterpret_cast<uint2*>(u_h)[idx] = hi;
    reinterpret_cast<uint2*>(u_l)[idx] = lo;
}

// ================= bf16x3 GEMM via mma.sync + cp.async pipeline =============
// C[M,N](+z) = alpha * A[M,K] * B[N,K]^T (+ Res), 3-term bf16 split.
// BM=128, BK=32 per stage, 2-stage cp.async double buffer. 256 thr = 8 warps.
// SMEM rows padded to 80B (5x16B) -> conflict-free ldmatrix phases.
template<int BN, int WM, int WN>
__global__ void __launch_bounds__(256, 2)
gemm_mma_kernel(const __nv_bfloat16* __restrict__ Ah,
                const __nv_bfloat16* __restrict__ Al, long lda, long strideAz,
                const __nv_bfloat16* __restrict__ Bh,
                const __nv_bfloat16* __restrict__ Bl, long ldb, long strideBz,
                float* __restrict__ C, long ldc, long strideCz,
                const float* __restrict__ Res,
                int K, float alpha)
{
    constexpr int BM = 128;
    constexpr int MF = WM / 16;
    constexpr int NF = WN / 8;
    constexpr int WMS = BM / WM;
    constexpr int ROWB = 80;
    constexpr int ASZ = BM * ROWB;          // per-term A bytes
    constexpr int BSZ = BN * ROWB;
    constexpr int STAGE = 2*ASZ + 2*BSZ;

    extern __shared__ char smem[];
    const uint32_t s0 = smem_to_u32(smem);

    int tid = threadIdx.x, wid = tid >> 5, lane = tid & 31;
    int wm = wid % WMS, wn = wid / WMS;
    int z = blockIdx.z;
    Ah += (long)z * strideAz;  Al += (long)z * strideAz;
    Bh += (long)z * strideBz;  Bl += (long)z * strideBz;
    C  += (long)z * strideCz;
    const float* R = Res ? Res + (long)z * strideCz : nullptr;

    const int m0 = blockIdx.y * BM;
    const int n0 = blockIdx.x * BN;

    // prefetch lambda: stage buffer `st`, k offset k0
    auto prefetch = [&](int st, int k0) {
        uint32_t sb = s0 + st * STAGE;
        #pragma unroll
        for (int i = tid; i < BM*8; i += 256) {          // A: 2 terms x 128 x 4
            int term = i >> 9, rem = i & 511;
            int r = rem >> 2, c = rem & 3;
            const __nv_bfloat16* src = (term ? Al : Ah) + (long)(m0 + r)*lda + k0 + c*8;
            cp_async16(sb + term*ASZ + r*ROWB + c*16, src);
        }
        #pragma unroll
        for (int i = tid; i < BN*8; i += 256) {          // B: 2 terms x BN x 4
            int term = i >= BN*4;
            int rem = term ? i - BN*4 : i;
            int r = rem >> 2, c = rem & 3;
            const __nv_bfloat16* src = (term ? Bl : Bh) + (long)(n0 + r)*ldb + k0 + c*8;
            cp_async16(sb + 2*ASZ + term*BSZ + r*ROWB + c*16, src);
        }
    };

    float d[MF][NF][4] = {};
    const int lm16 = lane & 15, lq = lane >> 4;
    const int lb8  = lane & 7,  lh = (lane >> 3) & 1;

    const int nsteps = K >> 5;
    prefetch(0, 0);
    CP_COMMIT();

    for (int s = 0; s < nsteps; s++) {
        if (s + 1 < nsteps) prefetch((s + 1) & 1, (s + 1) << 5);
        CP_COMMIT();
        CP_WAIT1();
        __syncthreads();

        uint32_t sb  = s0 + (s & 1) * STAGE;
        uint32_t sAh = sb, sAl = sb + ASZ;
        uint32_t sBh = sb + 2*ASZ, sBl = sb + 2*ASZ + BSZ;

        #pragma unroll
        for (int kk = 0; kk < 32; kk += 16) {
            uint32_t ah[MF][4], al[MF][4];
            #pragma unroll
            for (int fm = 0; fm < MF; fm++) {
                uint32_t off = (uint32_t)((wm*WM + fm*16 + lm16)*ROWB + (kk + lq*8)*2);
                ldsm_x4(ah[fm], sAh + off);
                ldsm_x4(al[fm], sAl + off);
            }
            #pragma unroll
            for (int fn = 0; fn < NF; fn++) {
                uint32_t bh[2], bl[2];
                uint32_t off = (uint32_t)((wn*WN + fn*8 + lb8)*ROWB + (kk + lh*8)*2);
                ldsm_x2(bh, sBh + off);
                ldsm_x2(bl, sBl + off);
                #pragma unroll
                for (int fm = 0; fm < MF; fm++) {
                    mma_bf16(d[fm][fn], ah[fm], bh);
                    mma_bf16(d[fm][fn], ah[fm], bl);
                    mma_bf16(d[fm][fn], al[fm], bh);
                }
            }
        }
        __syncthreads();
    }

    // ---- epilogue: alpha scale + optional residual ----
    #pragma unroll
    for (int fm = 0; fm < MF; fm++) {
        #pragma unroll
        for (int fn = 0; fn < NF; fn++) {
            long row = m0 + wm*WM + fm*16 + (lane >> 2);
            long col = n0 + wn*WN + fn*8 + (lane & 3)*2;
            float2 v0 = make_float2(d[fm][fn][0]*alpha, d[fm][fn][1]*alpha);
            float2 v1 = make_float2(d[fm][fn][2]*alpha, d[fm][fn][3]*alpha);
            if (R) {
                float2 r0 = *reinterpret_cast<const float2*>(R + row*ldc + col);
                float2 r1 = *reinterpret_cast<const float2*>(R + (row+8)*ldc + col);
                v0.x += r0.x; v0.y += r0.y; v1.x += r1.x; v1.y += r1.y;
            }
            *reinterpret_cast<float2*>(C + row*ldc + col)     = v0;
            *reinterpret_cast<float2*>(C + (row+8)*ldc + col) = v1;
        }
    }
}

// ================= host orchestration =======================================
extern "C" void kernel_launch(void* const* d_in, const int* in_sizes, int n_in,
                              void* d_out, int out_size) {
    const int*   tok     = (const int*)  d_in[0];
    const int*   pos     = (const int*)  d_in[1];
    const float* emb     = (const float*)d_in[2];
    const float* attn_nw = (const float*)d_in[3];
    const float* wq      = (const float*)d_in[4];
    const float* wk      = (const float*)d_in[5];
    const float* wv      = (const float*)d_in[6];
    const float* wo      = (const float*)d_in[7];
    const float* ff_nw   = (const float*)d_in[8];
    const float* w1      = (const float*)d_in[9];
    const float* w2      = (const float*)d_in[10];
    const float* w3      = (const float*)d_in[11];
    const float* norm_w  = (const float*)d_in[12];
    float* out = (float*)d_out;

    float *x, *q, *k, *v, *ot, *sc, *u, *t, *cb, *sb;
    cudaGetSymbolAddress((void**)&x,  g_x);
    cudaGetSymbolAddress((void**)&q,  g_q);
    cudaGetSymbolAddress((void**)&k,  g_k);
    cudaGetSymbolAddress((void**)&v,  g_v);
    cudaGetSymbolAddress((void**)&ot, g_ot);
    cudaGetSymbolAddress((void**)&sc, g_sc);
    cudaGetSymbolAddress((void**)&u,  g_u);
    cudaGetSymbolAddress((void**)&t,  g_t);
    cudaGetSymbolAddress((void**)&cb, g_cos);
    cudaGetSymbolAddress((void**)&sb, g_sin);

    __nv_bfloat16 *ah, *al, *uh, *ul, *qhh, *qhl, *khh, *khl, *vth, *vtl, *ph, *pl;
    cudaGetSymbolAddress((void**)&ah,  a_h);  cudaGetSymbolAddress((void**)&al,  a_l);
    cudaGetSymbolAddress((void**)&uh,  u_h);  cudaGetSymbolAddress((void**)&ul,  u_l);
    cudaGetSymbolAddress((void**)&qhh, qh_h); cudaGetSymbolAddress((void**)&qhl, qh_l);
    cudaGetSymbolAddress((void**)&khh, kh_h); cudaGetSymbolAddress((void**)&khl, kh_l);
    cudaGetSymbolAddress((void**)&vth, vt_h); cudaGetSymbolAddress((void**)&vtl, vt_l);
    cudaGetSymbolAddress((void**)&ph,  p_h);  cudaGetSymbolAddress((void**)&pl,  p_l);

    __nv_bfloat16 *wqh,*wql,*wkh,*wkl,*wvh,*wvl,*woh,*wol,*w1h,*w1l,*w3h,*w3l,*w2h,*w2l,*eh,*el;
    cudaGetSymbolAddress((void**)&wqh, wq_h); cudaGetSymbolAddress((void**)&wql, wq_l);
    cudaGetSymbolAddress((void**)&wkh, wk_h); cudaGetSymbolAddress((void**)&wkl, wk_l);
    cudaGetSymbolAddress((void**)&wvh, wv_h); cudaGetSymbolAddress((void**)&wvl, wv_l);
    cudaGetSymbolAddress((void**)&woh, wo_h); cudaGetSymbolAddress((void**)&wol, wo_l);
    cudaGetSymbolAddress((void**)&w1h, w1_h); cudaGetSymbolAddress((void**)&w1l, w1_l);
    cudaGetSymbolAddress((void**)&w3h, w3_h); cudaGetSymbolAddress((void**)&w3l, w3_l);
    cudaGetSymbolAddress((void**)&w2h, w2_h); cudaGetSymbolAddress((void**)&w2l, w2_l);
    cudaGetSymbolAddress((void**)&eh,  emb_h); cudaGetSymbolAddress((void**)&el,  emb_l);

    const int TPB = 256;
    // dynamic smem sizes: 2 stages of (2*A + 2*B)
    constexpr int SMEM128 = 2 * (2*128*80 + 2*128*80);   // 81920
    constexpr int SMEM64  = 2 * (2*128*80 + 2*64*80);    // 61440
    cudaFuncSetAttribute((const void*)gemm_mma_kernel<128,64,32>,
                         cudaFuncAttributeMaxDynamicSharedMemorySize, SMEM128);
    cudaFuncSetAttribute((const void*)gemm_mma_kernel<64,32,32>,
                         cudaFuncAttributeMaxDynamicSharedMemorySize, SMEM64);

    // ---- weight + embed conversion to bf16 hi/lo (vectorized) ----
    auto conv = [&](const float* s, __nv_bfloat16* dh, __nv_bfloat16* dl, long n) {
        long n4 = n >> 2;
        convert_split_kernel<<<(int)((n4 + TPB-1)/TPB), TPB>>>(s, dh, dl, n4);
    };
    conv(wq, wqh, wql, (long)LL*DD*DD);
    conv(wk, wkh, wkl, (long)LL*DD*DD);
    conv(wv, wvh, wvl, (long)LL*DD*DD);
    conv(wo, woh, wol, (long)LL*DD*DD);
    conv(w1, w1h, w1l, (long)LL*DFFN*DD);
    conv(w3, w3h, w3l, (long)LL*DFFN*DD);
    conv(w2, w2h, w2l, (long)LL*DD*DFFN);
    conv(emb, eh, el,  (long)NVOC*DD);

    embed_gather_kernel<<<(NTOK*DD/4 + TPB-1)/TPB, TPB>>>(tok, emb, x);
    rope_table_kernel<<<(NTOK*32 + TPB-1)/TPB, TPB>>>(pos, cb, sb);

    dim3 gProj(DD/128,   NTOK/128);        // (8,16)
    dim3 gFF  (DFFN/128, NTOK/128);        // (32,16)
    dim3 gHead(NVOC/128, NTOK/128);        // (128,16)
    dim3 gQK  (TT/128, TT/128, NZ);        // (8,8,32)
    dim3 gPV  (1,      TT/128, NZ);        // (1,8,32)

    for (int l = 0; l < LL; l++) {
        long woff  = (long)l*DD*DD;
        long wfoff = (long)l*DFFN*DD;

        // ---- attention ----
        rmsnorm_bf16_kernel<<<NTOK, TPB>>>(x, attn_nw + (long)l*DD, ah, al);
        gemm_mma_kernel<128,64,32><<<gProj, TPB, SMEM128>>>(
            ah, al, DD, 0, wqh+woff, wql+woff, DD, 0, q, DD, 0, nullptr, DD, 1.f);
        gemm_mma_kernel<128,64,32><<<gProj, TPB, SMEM128>>>(
            ah, al, DD, 0, wkh+woff, wkl+woff, DD, 0, k, DD, 0, nullptr, DD, 1.f);
        gemm_mma_kernel<128,64,32><<<gProj, TPB, SMEM128>>>(
            ah, al, DD, 0, wvh+woff, wvl+woff, DD, 0, v, DD, 0, nullptr, DD, 1.f);
        rope_convert_qk_kernel<<<(NTOK*HH*32 + TPB-1)/TPB, TPB>>>(q, k, cb, sb);
        vt_convert_kernel<<<(int)(((long)NZ*HDIM*TT/2 + TPB-1)/TPB), TPB>>>(v);
        gemm_mma_kernel<128,64,32><<<gQK, TPB, SMEM128>>>(
            qhh, qhl, HDIM, (long)TT*HDIM,
            khh, khl, HDIM, (long)TT*HDIM,
            sc, TT, (long)TT*TT, nullptr, HDIM, 0.125f);
        softmax_bf16_kernel<<<NZ*TT, TPB>>>(sc);
        gemm_mma_kernel<64,32,32><<<gPV, TPB, SMEM64>>>(
            ph, pl, TT, (long)TT*TT,
            vth, vtl, TT, (long)HDIM*TT,
            ot, HDIM, (long)TT*HDIM, nullptr, TT, 1.f);
        o_convert_kernel<<<(NTOK*DD/4 + TPB-1)/TPB, TPB>>>(ot);
        gemm_mma_kernel<128,64,32><<<gProj, TPB, SMEM128>>>(
            ah, al, DD, 0, woh+woff, wol+woff, DD, 0, x, DD, 0, x, DD, 1.f);

        // ---- SwiGLU FFN ----
        rmsnorm_bf16_kernel<<<NTOK, TPB>>>(x, ff_nw + (long)l*DD, ah, al);
        gemm_mma_kernel<128,64,32><<<gFF, TPB, SMEM128>>>(
            ah, al, DD, 0, w1h+wfoff, w1l+wfoff, DD, 0, u, DFFN, 0, nullptr, DD, 1.f);
        gemm_mma_kernel<128,64,32><<<gFF, TPB, SMEM128>>>(
            ah, al, DD, 0, w3h+wfoff, w3l+wfoff, DD, 0, t, DFFN, 0, nullptr, DD, 1.f);
        swiglu_bf16_kernel<<<(int)(((long)NTOK*DFFN/4 + TPB-1)/TPB), TPB>>>(u, t);
        gemm_mma_kernel<128,64,32><<<gProj, TPB, SMEM128>>>(
            uh, ul, DFFN, 0, w2h+wfoff, w2l+wfoff, DFFN, 0, x, DD, 0, x, DFFN, 1.f);
    }

    // ---- final norm + tied LM head ----
    rmsnorm_bf16_kernel<<<NTOK, TPB>>>(x, norm_w, ah, al);
    gemm_mma_kernel<128,64,32><<<gHead, TPB, SMEM128>>>(
        ah, al, DD, 0, eh, el, DD, 0, out, NVOC, 0, nullptr, DD, 1.f);
}